// round 1
// baseline (speedup 1.0000x reference)
#include <cuda_runtime.h>
#include <cuda_bf16.h>

// Problem constants
#define T_LEN 4096
#define E_DIM 1024
#define H_NUM 16
#define HD    64

// Scratch (allocation-free rule: __device__ globals)
__device__ float g_Q[(long)H_NUM * T_LEN * HD];            // 16 MB, head-major [h][t][d]
__device__ float g_K[(long)H_NUM * T_LEN * HD];            // 16 MB
__device__ float g_V[(long)H_NUM * T_LEN * HD];            // 16 MB
__device__ float g_P[(long)H_NUM * T_LEN * T_LEN];         // 1 GB, [h][t][s]
__device__ float g_CTX[(long)T_LEN * E_DIM];               // 16 MB, [t][e]

// ---------------------------------------------------------------------------
// Generic tiled SGEMM: C = (A * B(^T) + bias) * scale
//   A: (M x K) row-major, stride K
//   B: BT=true  -> (N x K) row-major, stride K (weight / key style)
//      BT=false -> (K x N) row-major, stride N (value style)
//   blockIdx.z selects a "head": per-head strides aH, bH, cH.
//   HEADM=true -> scatter columns into head-major layout [n/64][m][n%64]
// ---------------------------------------------------------------------------
template<int BM, int BN, int BK, int TM, int TN, bool BT, bool HEADM>
__global__ __launch_bounds__(256) void sgemm_k(
    const float* __restrict__ A, const float* __restrict__ B,
    const float* __restrict__ bias, float* __restrict__ C,
    int M, int N, int K, int ldc,
    long aH, long bH, long cH, float scale)
{
    constexpr int THREADS = 256;
    A += blockIdx.z * aH;
    B += blockIdx.z * bH;
    C += blockIdx.z * cH;

    __shared__ float As[BK][BM + 4];
    __shared__ float Bs[BK][BN + 4];

    const int tid = threadIdx.x;
    constexpr int TCOLS = BN / TN;
    const int ty = tid / TCOLS;
    const int tx = tid % TCOLS;
    const int m0 = ty * TM;
    const int n0 = tx * TN;
    const int gm0 = blockIdx.y * BM;
    const int gn0 = blockIdx.x * BN;

    float acc[TM][TN];
#pragma unroll
    for (int i = 0; i < TM; i++)
#pragma unroll
        for (int j = 0; j < TN; j++) acc[i][j] = 0.0f;

    for (int k0 = 0; k0 < K; k0 += BK) {
        // --- load A tile (BM x BK), transpose into As[k][m] ---
        constexpr int AV = (BM * BK) / (THREADS * 4);
#pragma unroll
        for (int i = 0; i < AV; i++) {
            int idx = (tid + i * THREADS) * 4;
            int m = idx / BK, kk = idx % BK;
            float4 t = *(const float4*)(A + (long)(gm0 + m) * K + k0 + kk);
            As[kk + 0][m] = t.x;
            As[kk + 1][m] = t.y;
            As[kk + 2][m] = t.z;
            As[kk + 3][m] = t.w;
        }
        // --- load B tile into Bs[k][n] ---
        constexpr int BV = (BN * BK) / (THREADS * 4);
#pragma unroll
        for (int i = 0; i < BV; i++) {
            int idx = (tid + i * THREADS) * 4;
            if (BT) {
                int n = idx / BK, kk = idx % BK;
                float4 t = *(const float4*)(B + (long)(gn0 + n) * K + k0 + kk);
                Bs[kk + 0][n] = t.x;
                Bs[kk + 1][n] = t.y;
                Bs[kk + 2][n] = t.z;
                Bs[kk + 3][n] = t.w;
            } else {
                int kk = idx / BN, n = idx % BN;
                *(float4*)&Bs[kk][n] =
                    *(const float4*)(B + (long)(k0 + kk) * N + gn0 + n);
            }
        }
        __syncthreads();

#pragma unroll
        for (int kk = 0; kk < BK; kk++) {
            float a[TM], b[TN];
#pragma unroll
            for (int i = 0; i < TM; i += 4)
                *(float4*)&a[i] = *(const float4*)&As[kk][m0 + i];
#pragma unroll
            for (int j = 0; j < TN; j += 4)
                *(float4*)&b[j] = *(const float4*)&Bs[kk][n0 + j];
#pragma unroll
            for (int i = 0; i < TM; i++)
#pragma unroll
                for (int j = 0; j < TN; j++)
                    acc[i][j] += a[i] * b[j];
        }
        __syncthreads();
    }

    // --- epilogue ---
#pragma unroll
    for (int i = 0; i < TM; i++) {
        const int m = gm0 + m0 + i;
#pragma unroll
        for (int j = 0; j < TN; j++) {
            const int n = gn0 + n0 + j;
            float v = acc[i][j];
            if (bias) v += bias[n];
            v *= scale;
            if (HEADM) {
                const int h = n >> 6;
                const int d = n & 63;
                C[(long)h * M * HD + (long)m * HD + d] = v;
            } else {
                C[(long)m * ldc + n] = v;
            }
        }
    }
}

// ---------------------------------------------------------------------------
// Row softmax in place. One block per row of length 4096. 256 threads.
// ---------------------------------------------------------------------------
__global__ __launch_bounds__(256) void softmax_k(float* __restrict__ P)
{
    float4* row = (float4*)(P + (long)blockIdx.x * T_LEN);
    const int tid = threadIdx.x;

    float4 v[4];
    float m = -3.4e38f;
#pragma unroll
    for (int j = 0; j < 4; j++) {
        v[j] = row[tid + j * 256];
        m = fmaxf(m, fmaxf(fmaxf(v[j].x, v[j].y), fmaxf(v[j].z, v[j].w)));
    }

    __shared__ float smax[8];
    __shared__ float ssum[8];
#pragma unroll
    for (int o = 16; o > 0; o >>= 1)
        m = fmaxf(m, __shfl_xor_sync(0xffffffffu, m, o));
    if ((tid & 31) == 0) smax[tid >> 5] = m;
    __syncthreads();
    const float bm = fmaxf(fmaxf(fmaxf(smax[0], smax[1]), fmaxf(smax[2], smax[3])),
                           fmaxf(fmaxf(smax[4], smax[5]), fmaxf(smax[6], smax[7])));

    float s = 0.0f;
#pragma unroll
    for (int j = 0; j < 4; j++) {
        v[j].x = __expf(v[j].x - bm);
        v[j].y = __expf(v[j].y - bm);
        v[j].z = __expf(v[j].z - bm);
        v[j].w = __expf(v[j].w - bm);
        s += v[j].x + v[j].y + v[j].z + v[j].w;
    }
#pragma unroll
    for (int o = 16; o > 0; o >>= 1)
        s += __shfl_xor_sync(0xffffffffu, s, o);
    if ((tid & 31) == 0) ssum[tid >> 5] = s;
    __syncthreads();
    const float bs = (ssum[0] + ssum[1]) + (ssum[2] + ssum[3]) +
                     (ssum[4] + ssum[5]) + (ssum[6] + ssum[7]);
    const float inv = 1.0f / bs;

#pragma unroll
    for (int j = 0; j < 4; j++) {
        v[j].x *= inv; v[j].y *= inv; v[j].z *= inv; v[j].w *= inv;
        row[tid + j * 256] = v[j];
    }
}

// ---------------------------------------------------------------------------
// attn_avg = (1/H) * sum_h P[h]  (float4 vectorized)
// ---------------------------------------------------------------------------
__global__ __launch_bounds__(256) void avg_k(const float* __restrict__ P,
                                             float* __restrict__ out)
{
    const long i = (long)blockIdx.x * 256 + threadIdx.x;   // float4 index
    const long TS4 = (long)T_LEN * T_LEN / 4;
    const float4* P4 = (const float4*)P;
    float4 acc = make_float4(0.f, 0.f, 0.f, 0.f);
#pragma unroll
    for (int h = 0; h < H_NUM; h++) {
        float4 t = P4[(long)h * TS4 + i];
        acc.x += t.x; acc.y += t.y; acc.z += t.z; acc.w += t.w;
    }
    acc.x *= 0.0625f; acc.y *= 0.0625f; acc.z *= 0.0625f; acc.w *= 0.0625f;
    ((float4*)out)[i] = acc;
}

// ---------------------------------------------------------------------------
// Launch
// ---------------------------------------------------------------------------
extern "C" void kernel_launch(void* const* d_in, const int* in_sizes, int n_in,
                              void* d_out, int out_size)
{
    const float* q_in = (const float*)d_in[0];
    const float* k_in = (const float*)d_in[1];
    const float* v_in = (const float*)d_in[2];
    const float* w    = (const float*)d_in[3];   // (3E, E)
    const float* b    = (const float*)d_in[4];   // (3E)
    const float* ow   = (const float*)d_in[5];   // (E, E)
    const float* ob   = (const float*)d_in[6];   // (E)
    float* out = (float*)d_out;

    float *Q, *K, *V, *P, *CTX;
    cudaGetSymbolAddress((void**)&Q,   g_Q);
    cudaGetSymbolAddress((void**)&K,   g_K);
    cudaGetSymbolAddress((void**)&V,   g_V);
    cudaGetSymbolAddress((void**)&P,   g_P);
    cudaGetSymbolAddress((void**)&CTX, g_CTX);

    const int T = T_LEN, E = E_DIM, H = H_NUM;
    const long EE = (long)E * E;
    dim3 blk(256);

    // QKV projections: X(T,E) @ W^T(E,E) + b  -> head-major [h][t][d]
    sgemm_k<128,128,16,8,8,true,true><<<dim3(E/128, T/128, 1), blk>>>(
        q_in, w,          b,         Q, T, E, E, 0, 0, 0, 0, 0.125f);  // Q /= sqrt(64)
    sgemm_k<128,128,16,8,8,true,true><<<dim3(E/128, T/128, 1), blk>>>(
        k_in, w + EE,     b + E,     K, T, E, E, 0, 0, 0, 0, 1.0f);
    sgemm_k<128,128,16,8,8,true,true><<<dim3(E/128, T/128, 1), blk>>>(
        v_in, w + 2*EE,   b + 2*E,   V, T, E, E, 0, 0, 0, 0, 1.0f);

    // scores: per head, Qh(T,64) @ Kh^T -> P[h](T,T)
    sgemm_k<128,128,16,8,8,true,false><<<dim3(T/128, T/128, H), blk>>>(
        Q, K, nullptr, P, T, T, HD, T,
        (long)T * HD, (long)T * HD, (long)T * T, 1.0f);

    // softmax rows (H*T rows of length T)
    softmax_k<<<H * T, 256>>>(P);

    // attn_avg -> second half of d_out
    avg_k<<<(int)(((long)T * T / 4) / 256), 256>>>(P, out + (long)T * E);

    // ctx: per head, P[h](T,T) @ Vh(T,64) -> CTX[:, h*64 : h*64+64]
    sgemm_k<128,64,16,8,4,false,false><<<dim3(1, T/128, H), blk>>>(
        P, V, nullptr, CTX, T, HD, T, E,
        (long)T * T, (long)T * HD, (long)HD, 1.0f);

    // out projection: CTX(T,E) @ OW^T + ob -> d_out[0 : T*E)
    sgemm_k<128,128,16,8,8,true,false><<<dim3(E/128, T/128, 1), blk>>>(
        CTX, ow, ob, out, T, E, E, E, 0, 0, 0, 1.0f);
}

// round 2
// speedup vs baseline: 1.8632x; 1.8632x over previous
#include <cuda_runtime.h>
#include <cstdint>

#define T_LEN 4096
#define E_DIM 1024
#define H_NUM 16
#define HD    64

// Scratch (allocation-free rule: __device__ globals)
__device__ float g_Q [(long)H_NUM * T_LEN * HD];   // [h][t][d]
__device__ float g_K [(long)H_NUM * T_LEN * HD];   // [h][t][d]
__device__ float g_Vt[(long)H_NUM * HD * T_LEN];   // [h][d][t]  (transposed!)
__device__ float g_P [(long)H_NUM * T_LEN * T_LEN];// [h][t][s]  1 GB
__device__ float g_CTX[(long)T_LEN * E_DIM];       // [t][e]

__device__ __forceinline__ uint32_t f2tf32(float x) {
    uint32_t r;
    asm("cvt.rna.tf32.f32 %0, %1;" : "=r"(r) : "f"(x));
    return r;
}

__device__ __forceinline__ void mma_tf32(float c[4],
    uint32_t a0, uint32_t a1, uint32_t a2, uint32_t a3,
    uint32_t b0, uint32_t b1)
{
    asm volatile(
        "mma.sync.aligned.m16n8k8.row.col.f32.tf32.tf32.f32 "
        "{%0,%1,%2,%3}, {%4,%5,%6,%7}, {%8,%9}, {%0,%1,%2,%3};"
        : "+f"(c[0]), "+f"(c[1]), "+f"(c[2]), "+f"(c[3])
        : "r"(a0), "r"(a1), "r"(a2), "r"(a3), "r"(b0), "r"(b1));
}

// ---------------------------------------------------------------------------
// TF32 tensor-core GEMM: C = (A * B^T + bias) * scale
//   A: (M x K) row-major, stride K.   B: (N x K) row-major, stride K.
//   blockIdx.z = head; per-head strides aH/bH/cH.
//   EPI 0: C[m*ldc+n]   EPI 1: head-scatter [h][m][d]   EPI 2: [h][d][m]
// ---------------------------------------------------------------------------
template<int BM, int BN, int WM, int WN, int EPI>
__global__ __launch_bounds__((BM/WM)*(BN/WN)*32)
void mma_gemm(const float* __restrict__ A, const float* __restrict__ B,
              const float* __restrict__ bias, float* __restrict__ C,
              int M, int N, int K, int ldc,
              long aH, long bH, long cH, float scale)
{
    constexpr int THREADS = (BM/WM)*(BN/WN)*32;
    constexpr int BK = 16;
    constexpr int MT = WM/16, NT = WN/8;
    constexpr int NWARP_N = BN/WN;

    A += blockIdx.z * aH;
    B += blockIdx.z * bH;
    C += blockIdx.z * cH;

    __shared__ uint32_t As[BK][BM + 8];
    __shared__ uint32_t Bs[BK][BN + 8];

    const int tid  = threadIdx.x;
    const int warp = tid >> 5, lane = tid & 31;
    const int wm0 = (warp / NWARP_N) * WM;
    const int wn0 = (warp % NWARP_N) * WN;
    const int gid = lane >> 2, tg = lane & 3;
    const int gm0 = blockIdx.y * BM, gn0 = blockIdx.x * BN;

    float acc[MT][NT][4];
#pragma unroll
    for (int i = 0; i < MT; i++)
#pragma unroll
        for (int j = 0; j < NT; j++)
#pragma unroll
            for (int q = 0; q < 4; q++) acc[i][j][q] = 0.0f;

    for (int k0 = 0; k0 < K; k0 += BK) {
        constexpr int AV = BM*BK/(THREADS*4);
#pragma unroll
        for (int i = 0; i < AV; i++) {
            int idx = (tid + i*THREADS) * 4;
            int m = idx / BK, kk = idx % BK;
            float4 t = *(const float4*)(A + (long)(gm0 + m)*K + k0 + kk);
            As[kk+0][m] = f2tf32(t.x);
            As[kk+1][m] = f2tf32(t.y);
            As[kk+2][m] = f2tf32(t.z);
            As[kk+3][m] = f2tf32(t.w);
        }
        constexpr int BV = BN*BK/(THREADS*4);
#pragma unroll
        for (int i = 0; i < BV; i++) {
            int idx = (tid + i*THREADS) * 4;
            int n = idx / BK, kk = idx % BK;
            float4 t = *(const float4*)(B + (long)(gn0 + n)*K + k0 + kk);
            Bs[kk+0][n] = f2tf32(t.x);
            Bs[kk+1][n] = f2tf32(t.y);
            Bs[kk+2][n] = f2tf32(t.z);
            Bs[kk+3][n] = f2tf32(t.w);
        }
        __syncthreads();

#pragma unroll
        for (int ks = 0; ks < BK; ks += 8) {
            uint32_t af[MT][4];
            uint32_t bf[NT][2];
#pragma unroll
            for (int i = 0; i < MT; i++) {
                int m = wm0 + i*16 + gid;
                af[i][0] = As[ks + tg    ][m];
                af[i][1] = As[ks + tg    ][m + 8];
                af[i][2] = As[ks + tg + 4][m];
                af[i][3] = As[ks + tg + 4][m + 8];
            }
#pragma unroll
            for (int j = 0; j < NT; j++) {
                int n = wn0 + j*8 + gid;
                bf[j][0] = Bs[ks + tg    ][n];
                bf[j][1] = Bs[ks + tg + 4][n];
            }
#pragma unroll
            for (int i = 0; i < MT; i++)
#pragma unroll
                for (int j = 0; j < NT; j++)
                    mma_tf32(acc[i][j], af[i][0], af[i][1], af[i][2], af[i][3],
                             bf[j][0], bf[j][1]);
        }
        __syncthreads();
    }

    // epilogue
#pragma unroll
    for (int i = 0; i < MT; i++) {
#pragma unroll
        for (int j = 0; j < NT; j++) {
#pragma unroll
            for (int h2 = 0; h2 < 2; h2++) {
                int m = gm0 + wm0 + i*16 + gid + h2*8;
                int n = gn0 + wn0 + j*8 + tg*2;
                float v0 = acc[i][j][h2*2 + 0];
                float v1 = acc[i][j][h2*2 + 1];
                if (bias) { v0 += bias[n]; v1 += bias[n+1]; }
                v0 *= scale; v1 *= scale;
                if (EPI == 0) {
                    *(float2*)(C + (long)m*ldc + n) = make_float2(v0, v1);
                } else if (EPI == 1) {          // [h][m][d]
                    int h = n >> 6, d = n & 63;
                    float* p = C + (long)h*M*HD + (long)m*HD + d;
                    p[0] = v0; p[1] = v1;
                } else {                        // [h][d][m]
                    int h = n >> 6, d = n & 63;
                    float* p = C + (long)h*HD*M + (long)d*M + m;
                    p[0] = v0; p[M] = v1;       // d and d+1 rows
                }
            }
        }
    }
}

// ---------------------------------------------------------------------------
// Fused softmax + head-average. One block per query position t.
// Loops all 16 heads: softmax row in place, accumulate avg, write avg row.
// ---------------------------------------------------------------------------
__global__ __launch_bounds__(1024) void softmax_avg_k(float* __restrict__ P,
                                                      float* __restrict__ avg)
{
    const int t = blockIdx.x;
    const int tid = threadIdx.x;
    const int warp = tid >> 5, lane = tid & 31;
    __shared__ float red[32];
    __shared__ float bcast;

    float4 acc = make_float4(0.f, 0.f, 0.f, 0.f);

#pragma unroll 1
    for (int h = 0; h < H_NUM; h++) {
        float4* row = (float4*)(P + ((long)h * T_LEN + t) * T_LEN);
        float4 v = row[tid];

        float m = fmaxf(fmaxf(v.x, v.y), fmaxf(v.z, v.w));
#pragma unroll
        for (int o = 16; o > 0; o >>= 1)
            m = fmaxf(m, __shfl_xor_sync(0xffffffffu, m, o));
        if (lane == 0) red[warp] = m;
        __syncthreads();
        if (warp == 0) {
            float x = red[lane];
#pragma unroll
            for (int o = 16; o > 0; o >>= 1)
                x = fmaxf(x, __shfl_xor_sync(0xffffffffu, x, o));
            if (lane == 0) bcast = x;
        }
        __syncthreads();
        const float bm = bcast;

        v.x = __expf(v.x - bm); v.y = __expf(v.y - bm);
        v.z = __expf(v.z - bm); v.w = __expf(v.w - bm);
        float s = v.x + v.y + v.z + v.w;
#pragma unroll
        for (int o = 16; o > 0; o >>= 1)
            s += __shfl_xor_sync(0xffffffffu, s, o);
        __syncthreads();   // protect red[] reuse
        if (lane == 0) red[warp] = s;
        __syncthreads();
        if (warp == 0) {
            float x = red[lane];
#pragma unroll
            for (int o = 16; o > 0; o >>= 1)
                x += __shfl_xor_sync(0xffffffffu, x, o);
            if (lane == 0) bcast = x;
        }
        __syncthreads();
        const float inv = 1.0f / bcast;

        v.x *= inv; v.y *= inv; v.z *= inv; v.w *= inv;
        row[tid] = v;
        acc.x += v.x; acc.y += v.y; acc.z += v.z; acc.w += v.w;
        __syncthreads();   // before red[] reuse next head
    }

    const float ih = 1.0f / H_NUM;
    acc.x *= ih; acc.y *= ih; acc.z *= ih; acc.w *= ih;
    ((float4*)(avg + (long)t * T_LEN))[tid] = acc;
}

// ---------------------------------------------------------------------------
extern "C" void kernel_launch(void* const* d_in, const int* in_sizes, int n_in,
                              void* d_out, int out_size)
{
    const float* q_in = (const float*)d_in[0];
    const float* k_in = (const float*)d_in[1];
    const float* v_in = (const float*)d_in[2];
    const float* w    = (const float*)d_in[3];   // (3E, E)
    const float* b    = (const float*)d_in[4];   // (3E)
    const float* ow   = (const float*)d_in[5];   // (E, E)
    const float* ob   = (const float*)d_in[6];   // (E)
    float* out = (float*)d_out;

    float *Q, *K, *Vt, *P, *CTX;
    cudaGetSymbolAddress((void**)&Q,   g_Q);
    cudaGetSymbolAddress((void**)&K,   g_K);
    cudaGetSymbolAddress((void**)&Vt,  g_Vt);
    cudaGetSymbolAddress((void**)&P,   g_P);
    cudaGetSymbolAddress((void**)&CTX, g_CTX);

    const int T = T_LEN, E = E_DIM, H = H_NUM;
    const long EE = (long)E * E;
    dim3 blk(256);

    // QKV projections (tensor cores). Q scaled by 1/sqrt(hd)=0.125.
    mma_gemm<128,128,32,64,1><<<dim3(E/128, T/128, 1), blk>>>(
        q_in, w,        b,       Q,  T, E, E, 0, 0, 0, 0, 0.125f);
    mma_gemm<128,128,32,64,1><<<dim3(E/128, T/128, 1), blk>>>(
        k_in, w + EE,   b + E,   K,  T, E, E, 0, 0, 0, 0, 1.0f);
    mma_gemm<128,128,32,64,2><<<dim3(E/128, T/128, 1), blk>>>(
        v_in, w + 2*EE, b + 2*E, Vt, T, E, E, 0, 0, 0, 0, 1.0f);

    // scores: P[h] = Qh (T,64) @ Kh^T (T,64)
    mma_gemm<128,128,32,64,0><<<dim3(T/128, T/128, H), blk>>>(
        Q, K, nullptr, P, T, T, HD, T,
        (long)T * HD, (long)T * HD, (long)T * T, 1.0f);

    // softmax + head-average (avg -> second half of d_out)
    softmax_avg_k<<<T, 1024>>>(P, out + (long)T * E);

    // ctx: CTX[:, h*64:(h+1)*64] = P[h] (T,T) @ Vt[h]^T (64,T)
    mma_gemm<128,64,32,32,0><<<dim3(1, T/128, H), blk>>>(
        P, Vt, nullptr, CTX, T, HD, T, E,
        (long)T * T, (long)HD * T, 64, 1.0f);

    // out projection
    mma_gemm<128,128,32,64,0><<<dim3(E/128, T/128, 1), blk>>>(
        CTX, ow, ob, out, T, E, E, E, 0, 0, 0, 1.0f);
}

// round 3
// speedup vs baseline: 2.2266x; 1.1950x over previous
#include <cuda_runtime.h>
#include <cstdint>

#define T_LEN 4096
#define E_DIM 1024
#define H_NUM 16
#define HD    64
#define NBX_SCORES 32   // gridDim.x of scores kernel (T/128)

// Scratch (allocation-free rule: __device__ globals)
__device__ float g_Q  [(long)H_NUM * T_LEN * HD];    // [h][t][d]
__device__ float g_K  [(long)H_NUM * T_LEN * HD];    // [h][t][d]
__device__ float g_Vt [(long)H_NUM * HD * T_LEN];    // [h][d][t]
__device__ float g_P  [(long)H_NUM * T_LEN * T_LEN]; // [h][t][s] unnormalized exp
__device__ float g_CTX[(long)T_LEN * E_DIM];         // [t][e]
__device__ float g_RSP[(long)H_NUM * T_LEN * NBX_SCORES]; // partial row sums
__device__ float g_INV[(long)H_NUM * T_LEN];         // 1/rowsum

__device__ __forceinline__ uint32_t f2tf32(float x) {
    uint32_t r;
    asm("cvt.rna.tf32.f32 %0, %1;" : "=r"(r) : "f"(x));
    return r;
}

__device__ __forceinline__ void mma_tf32(float c[4],
    uint32_t a0, uint32_t a1, uint32_t a2, uint32_t a3,
    uint32_t b0, uint32_t b1)
{
    asm volatile(
        "mma.sync.aligned.m16n8k8.row.col.f32.tf32.tf32.f32 "
        "{%0,%1,%2,%3}, {%4,%5,%6,%7}, {%8,%9}, {%0,%1,%2,%3};"
        : "+f"(c[0]), "+f"(c[1]), "+f"(c[2]), "+f"(c[3])
        : "r"(a0), "r"(a1), "r"(a2), "r"(a3), "r"(b0), "r"(b1));
}

// ---------------------------------------------------------------------------
// Double-buffered TF32 GEMM: C = op(A*B^T + bias)*scale
//   A (M,K) rm stride K; B (N,K) rm stride K. bz = head (strides aH/bH/cH/riH).
//   EPI 0: C[m*ldc+n];  1: [h][m][d];  2: [h][d][m]
//   EXPSUM: v=exp(v-20), emit per-block partial row sums to rsp
//   NORMA : scale A row m by rowinv[m] during load
// ---------------------------------------------------------------------------
template<int BM, int BN, int BK, int WARPS_M, int WARPS_N,
         int EPI, bool EXPSUM, bool NORMA>
__global__ __launch_bounds__(WARPS_M*WARPS_N*32)
void gemm_k(const float* __restrict__ A, const float* __restrict__ B,
            const float* __restrict__ bias, float* __restrict__ C,
            const float* __restrict__ rowinv, float* __restrict__ rsp,
            int M, int N, int K, int ldc,
            long aH, long bH, long cH, long riH, float scale)
{
    constexpr int THREADS = WARPS_M*WARPS_N*32;
    constexpr int WM = BM/WARPS_M, WN = BN/WARPS_N;
    constexpr int MT = WM/16, NT = WN/8;
    constexpr int AV = BM*BK/(THREADS*4);
    constexpr int BV = BN*BK/(THREADS*4);

    A += blockIdx.z * aH;
    B += blockIdx.z * bH;
    C += blockIdx.z * cH;
    if (NORMA) rowinv += blockIdx.z * riH;

    __shared__ uint32_t As[2][BK][BM + 8];
    __shared__ uint32_t Bs[2][BK][BN + 8];
    __shared__ float    srs[WARPS_N][BM];

    const int tid  = threadIdx.x;
    const int warp = tid >> 5, lane = tid & 31;
    const int wm0 = (warp / WARPS_N) * WM;
    const int wn0 = (warp % WARPS_N) * WN;
    const int gid = lane >> 2, tg = lane & 3;
    const int gm0 = blockIdx.y * BM, gn0 = blockIdx.x * BN;

    int am[AV], ak[AV], bn[BV], bk[BV];
    float ainv[AV];
#pragma unroll
    for (int i = 0; i < AV; i++) {
        int idx = (tid + i*THREADS) * 4;
        am[i] = idx / BK; ak[i] = idx % BK;
        ainv[i] = NORMA ? rowinv[gm0 + am[i]] : 1.0f;
    }
#pragma unroll
    for (int i = 0; i < BV; i++) {
        int idx = (tid + i*THREADS) * 4;
        bn[i] = idx / BK; bk[i] = idx % BK;
    }

    float4 ra[AV], rb[BV];
    auto loadg = [&](int k0) {
#pragma unroll
        for (int i = 0; i < AV; i++)
            ra[i] = *(const float4*)(A + (long)(gm0 + am[i])*K + k0 + ak[i]);
#pragma unroll
        for (int i = 0; i < BV; i++)
            rb[i] = *(const float4*)(B + (long)(gn0 + bn[i])*K + k0 + bk[i]);
    };
    auto sts = [&](int buf) {
#pragma unroll
        for (int i = 0; i < AV; i++) {
            As[buf][ak[i]+0][am[i]] = f2tf32(ra[i].x * ainv[i]);
            As[buf][ak[i]+1][am[i]] = f2tf32(ra[i].y * ainv[i]);
            As[buf][ak[i]+2][am[i]] = f2tf32(ra[i].z * ainv[i]);
            As[buf][ak[i]+3][am[i]] = f2tf32(ra[i].w * ainv[i]);
        }
#pragma unroll
        for (int i = 0; i < BV; i++) {
            Bs[buf][bk[i]+0][bn[i]] = f2tf32(rb[i].x);
            Bs[buf][bk[i]+1][bn[i]] = f2tf32(rb[i].y);
            Bs[buf][bk[i]+2][bn[i]] = f2tf32(rb[i].z);
            Bs[buf][bk[i]+3][bn[i]] = f2tf32(rb[i].w);
        }
    };

    float acc[MT][NT][4];
#pragma unroll
    for (int i = 0; i < MT; i++)
#pragma unroll
        for (int j = 0; j < NT; j++)
#pragma unroll
            for (int q = 0; q < 4; q++) acc[i][j][q] = 0.0f;

    const int NI = K / BK;
    loadg(0);
    sts(0);
#pragma unroll 1
    for (int it = 0; it < NI; ++it) {
        __syncthreads();
        if (it + 1 < NI) loadg((it + 1) * BK);
        const int buf = it & 1;
#pragma unroll
        for (int ks = 0; ks < BK; ks += 8) {
            uint32_t af[MT][4], bf[NT][2];
#pragma unroll
            for (int i = 0; i < MT; i++) {
                int m = wm0 + i*16 + gid;
                af[i][0] = As[buf][ks + tg    ][m];
                af[i][1] = As[buf][ks + tg    ][m + 8];
                af[i][2] = As[buf][ks + tg + 4][m];
                af[i][3] = As[buf][ks + tg + 4][m + 8];
            }
#pragma unroll
            for (int j = 0; j < NT; j++) {
                int n = wn0 + j*8 + gid;
                bf[j][0] = Bs[buf][ks + tg    ][n];
                bf[j][1] = Bs[buf][ks + tg + 4][n];
            }
#pragma unroll
            for (int i = 0; i < MT; i++)
#pragma unroll
                for (int j = 0; j < NT; j++)
                    mma_tf32(acc[i][j], af[i][0], af[i][1], af[i][2], af[i][3],
                             bf[j][0], bf[j][1]);
        }
        if (it + 1 < NI) sts(buf ^ 1);
    }

    // ---- epilogue ----
    float rsum[MT][2];
    if (EXPSUM) {
#pragma unroll
        for (int i = 0; i < MT; i++) { rsum[i][0] = 0.f; rsum[i][1] = 0.f; }
    }
#pragma unroll
    for (int i = 0; i < MT; i++) {
#pragma unroll
        for (int j = 0; j < NT; j++) {
#pragma unroll
            for (int h2 = 0; h2 < 2; h2++) {
                int m = gm0 + wm0 + i*16 + gid + h2*8;
                int n = gn0 + wn0 + j*8 + tg*2;
                float v0 = acc[i][j][h2*2 + 0];
                float v1 = acc[i][j][h2*2 + 1];
                if (bias) { v0 += bias[n]; v1 += bias[n+1]; }
                v0 *= scale; v1 *= scale;
                if (EXPSUM) {
                    v0 = __expf(v0 - 20.0f);
                    v1 = __expf(v1 - 20.0f);
                    rsum[i][h2] += v0 + v1;
                }
                if (EPI == 0) {
                    *(float2*)(C + (long)m*ldc + n) = make_float2(v0, v1);
                } else if (EPI == 1) {          // [h][m][d]
                    int h = n >> 6, d = n & 63;
                    float* p = C + (long)h*M*HD + (long)m*HD + d;
                    p[0] = v0; p[1] = v1;
                } else {                        // [h][d][m]
                    int h = n >> 6, d = n & 63;
                    float* p = C + (long)h*HD*M + (long)d*M + m;
                    p[0] = v0; p[M] = v1;
                }
            }
        }
    }
    if (EXPSUM) {
#pragma unroll
        for (int i = 0; i < MT; i++)
#pragma unroll
            for (int h2 = 0; h2 < 2; h2++)
#pragma unroll
                for (int o = 1; o < 4; o <<= 1)
                    rsum[i][h2] += __shfl_xor_sync(0xffffffffu, rsum[i][h2], o);
        if (tg == 0) {
            const int wn = warp % WARPS_N;
#pragma unroll
            for (int i = 0; i < MT; i++)
#pragma unroll
                for (int h2 = 0; h2 < 2; h2++)
                    srs[wn][wm0 + i*16 + h2*8 + gid] = rsum[i][h2];
        }
        __syncthreads();
        if (tid < BM) {
            float s = 0.f;
#pragma unroll
            for (int wn = 0; wn < WARPS_N; wn++) s += srs[wn][tid];
            rsp[((long)blockIdx.z*M + gm0 + tid)*gridDim.x + blockIdx.x] = s;
        }
    }
}

// ---------------------------------------------------------------------------
// inv[row] = 1 / sum_{b<32} part[row*32+b]   (one warp per row, deterministic)
// ---------------------------------------------------------------------------
__global__ __launch_bounds__(256) void invred_k(const float* __restrict__ part,
                                                float* __restrict__ inv)
{
    const int warp = threadIdx.x >> 5, lane = threadIdx.x & 31;
    const long row = (long)blockIdx.x * 8 + warp;
    float s = part[row * 32 + lane];
#pragma unroll
    for (int o = 16; o > 0; o >>= 1)
        s += __shfl_xor_sync(0xffffffffu, s, o);
    if (lane == 0) inv[row] = 1.0f / s;
}

// ---------------------------------------------------------------------------
// avg[t][s] = (1/H) * sum_h P[h][t][s] * inv[h][t]
// ---------------------------------------------------------------------------
__global__ __launch_bounds__(1024) void avg_k(const float* __restrict__ P,
                                              const float* __restrict__ inv,
                                              float* __restrict__ out)
{
    const int t = blockIdx.x, tid = threadIdx.x;
    const long TS4 = (long)T_LEN * T_LEN / 4;
    const float4* P4 = (const float4*)P + (long)t * (T_LEN/4) + tid;
    float4 acc = make_float4(0.f, 0.f, 0.f, 0.f);
#pragma unroll
    for (int h = 0; h < H_NUM; h++) {
        const float iv = inv[h * T_LEN + t] * (1.0f / H_NUM);
        float4 p = P4[(long)h * TS4];
        acc.x += p.x * iv; acc.y += p.y * iv;
        acc.z += p.z * iv; acc.w += p.w * iv;
    }
    ((float4*)(out + (long)t * T_LEN))[tid] = acc;
}

// ---------------------------------------------------------------------------
extern "C" void kernel_launch(void* const* d_in, const int* in_sizes, int n_in,
                              void* d_out, int out_size)
{
    const float* q_in = (const float*)d_in[0];
    const float* k_in = (const float*)d_in[1];
    const float* v_in = (const float*)d_in[2];
    const float* w    = (const float*)d_in[3];
    const float* b    = (const float*)d_in[4];
    const float* ow   = (const float*)d_in[5];
    const float* ob   = (const float*)d_in[6];
    float* out = (float*)d_out;

    float *Q, *K, *Vt, *P, *CTX, *RSP, *INV;
    cudaGetSymbolAddress((void**)&Q,   g_Q);
    cudaGetSymbolAddress((void**)&K,   g_K);
    cudaGetSymbolAddress((void**)&Vt,  g_Vt);
    cudaGetSymbolAddress((void**)&P,   g_P);
    cudaGetSymbolAddress((void**)&CTX, g_CTX);
    cudaGetSymbolAddress((void**)&RSP, g_RSP);
    cudaGetSymbolAddress((void**)&INV, g_INV);

    const int T = T_LEN, E = E_DIM, H = H_NUM;
    const long EE = (long)E * E;
    dim3 blk(256);

    // QKV projections
    gemm_k<128,128,16,2,4,1,false,false><<<dim3(E/128, T/128, 1), blk>>>(
        q_in, w,        b,       Q,  nullptr, nullptr, T, E, E, 0, 0,0,0,0, 0.125f);
    gemm_k<128,128,16,2,4,1,false,false><<<dim3(E/128, T/128, 1), blk>>>(
        k_in, w + EE,   b + E,   K,  nullptr, nullptr, T, E, E, 0, 0,0,0,0, 1.0f);
    gemm_k<128,128,16,2,4,2,false,false><<<dim3(E/128, T/128, 1), blk>>>(
        v_in, w + 2*EE, b + 2*E, Vt, nullptr, nullptr, T, E, E, 0, 0,0,0,0, 1.0f);

    // scores + exp + partial row sums:  P[h] = exp(Qh Kh^T - 20)
    gemm_k<128,128,16,2,4,0,true,false><<<dim3(T/128, T/128, H), blk>>>(
        Q, K, nullptr, P, nullptr, RSP, T, T, HD, T,
        (long)T*HD, (long)T*HD, (long)T*T, 0, 1.0f);

    // row-sum reduce -> inv
    invred_k<<<(H*T)/8, 256>>>(RSP, INV);

    // head-average -> second half of d_out
    avg_k<<<T, 1024>>>(P, INV, out + (long)T * E);

    // ctx: CTX[:, h*64:(h+1)*64] = (P[h] * inv) @ Vt[h]^T
    gemm_k<128,64,16,4,2,0,false,true><<<dim3(1, T/128, H), blk>>>(
        P, Vt, nullptr, CTX, INV, nullptr, T, HD, T, E,
        (long)T*T, (long)HD*T, 64, T, 1.0f);

    // out projection
    gemm_k<128,128,16,2,4,0,false,false><<<dim3(E/128, T/128, 1), blk>>>(
        CTX, ow, ob, out, nullptr, nullptr, T, E, E, E, 0,0,0,0, 1.0f);
}

// round 4
// speedup vs baseline: 2.3692x; 1.0641x over previous
#include <cuda_runtime.h>
#include <cstdint>

#define T_LEN 4096
#define E_DIM 1024
#define H_NUM 16
#define HD    64
#define NBX_SCORES 32   // gridDim.x of scores kernel (T/128)

// Scratch (allocation-free rule: __device__ globals)
__device__ float g_Q  [(long)H_NUM * T_LEN * HD];    // [h][t][d]
__device__ float g_K  [(long)H_NUM * T_LEN * HD];    // [h][t][d]
__device__ float g_Vt [(long)H_NUM * HD * T_LEN];    // [h][d][t]
__device__ float g_P  [(long)H_NUM * T_LEN * T_LEN]; // [h][t][s] unnormalized exp
__device__ float g_CTX[(long)T_LEN * E_DIM];         // [t][e]
__device__ float g_RSP[(long)H_NUM * T_LEN * NBX_SCORES]; // partial row sums
__device__ float g_INV[(long)H_NUM * T_LEN];         // 1/rowsum

__device__ __forceinline__ uint32_t f2tf32(float x) {
    uint32_t r;
    asm("cvt.rna.tf32.f32 %0, %1;" : "=r"(r) : "f"(x));
    return r;
}

__device__ __forceinline__ void mma_tf32(float c[4],
    uint32_t a0, uint32_t a1, uint32_t a2, uint32_t a3,
    uint32_t b0, uint32_t b1)
{
    asm volatile(
        "mma.sync.aligned.m16n8k8.row.col.f32.tf32.tf32.f32 "
        "{%0,%1,%2,%3}, {%4,%5,%6,%7}, {%8,%9}, {%0,%1,%2,%3};"
        : "+f"(c[0]), "+f"(c[1]), "+f"(c[2]), "+f"(c[3])
        : "r"(a0), "r"(a1), "r"(a2), "r"(a3), "r"(b0), "r"(b1));
}

// ===========================================================================
// Specialized scores kernel: P[h] tile = exp(Q K^T - 20), partial row sums.
// K = 64 loaded one-shot into FRAGMENT-MAJOR smem:
//   Asf[k8][mt][lane][4]  (16B/lane -> LDS.128)
//   Bsf[k8][nt][lane][2]  ( 8B/lane -> LDS.64)
// lane rotated by k8 (A) / 2*k8 (B) to reduce STS conflicts; rotation is a
// per-block lane permutation so consumer reads stay conflict-free.
// 256 threads, 8 warps (2x4), warp tile 64x32, block tile 128x128.
// ===========================================================================
__global__ __launch_bounds__(256, 2)
void scores_k(const float* __restrict__ Q, const float* __restrict__ Kp,
              float* __restrict__ P, float* __restrict__ rsp)
{
    extern __shared__ uint32_t smem[];
    uint32_t* Asf = smem;                 // 8*8*32*4  = 8192 u32 (32 KB)
    uint32_t* Bsf = smem + 8192;          // 8*16*32*2 = 8192 u32 (32 KB)
    float*    srs = (float*)(smem + 16384); // 4*128 floats (2 KB)

    const int tid  = threadIdx.x;
    const int warp = tid >> 5, lane = tid & 31;
    const int gid = lane >> 2, tg = lane & 3;
    const int wm0 = (warp >> 2) * 64;     // WARPS_M=2
    const int wn0 = (warp & 3) * 32;      // WARPS_N=4
    const int gm0 = blockIdx.y * 128, gn0 = blockIdx.x * 128;

    const float* Ah = Q  + (long)blockIdx.z * T_LEN * HD + (long)gm0 * HD;
    const float* Bh = Kp + (long)blockIdx.z * T_LEN * HD + (long)gn0 * HD;

    // ---- load + convert + fragment-scatter (A: 128x64, B: 128x64) ----
#pragma unroll
    for (int i = 0; i < 8; i++) {
        const int idx = (tid + i * 256) * 4;
        const int m = idx >> 6, k = idx & 63;
        const int k8 = k >> 3, khi = (k >> 2) & 1;   // c>>2 within k8 group
        float4 t = *(const float4*)(Ah + m * 64 + k);
        const int r = m & 15, mt = m >> 4;
        const int rega = (r >> 3) + 2 * khi;
        const int lbase = (r & 7) * 4;
        uint32_t* dst = Asf + ((k8 * 8 + mt) * 32) * 4 + rega;
        dst[(((lbase + 0) + k8) & 31) * 4] = f2tf32(t.x);
        dst[(((lbase + 1) + k8) & 31) * 4] = f2tf32(t.y);
        dst[(((lbase + 2) + k8) & 31) * 4] = f2tf32(t.z);
        dst[(((lbase + 3) + k8) & 31) * 4] = f2tf32(t.w);
    }
#pragma unroll
    for (int i = 0; i < 8; i++) {
        const int idx = (tid + i * 256) * 4;
        const int n = idx >> 6, k = idx & 63;
        const int k8 = k >> 3, khi = (k >> 2) & 1;
        float4 t = *(const float4*)(Bh + n * 64 + k);
        const int nt = n >> 3;
        const int lbase = (n & 7) * 4;
        uint32_t* dst = Bsf + ((k8 * 16 + nt) * 32) * 2 + khi;
        dst[(((lbase + 0) + 2 * k8) & 31) * 2] = f2tf32(t.x);
        dst[(((lbase + 1) + 2 * k8) & 31) * 2] = f2tf32(t.y);
        dst[(((lbase + 2) + 2 * k8) & 31) * 2] = f2tf32(t.z);
        dst[(((lbase + 3) + 2 * k8) & 31) * 2] = f2tf32(t.w);
    }
    __syncthreads();

    // ---- mainloop: 8 k-steps, 16 mmas each ----
    float acc[4][4][4];
#pragma unroll
    for (int i = 0; i < 4; i++)
#pragma unroll
        for (int j = 0; j < 4; j++)
#pragma unroll
            for (int q = 0; q < 4; q++) acc[i][j][q] = 0.0f;

#pragma unroll
    for (int ks = 0; ks < 8; ks++) {
        uint4 af[4];
        uint2 bf[4];
        const int la = (lane + ks) & 31;
        const int lb = (lane + 2 * ks) & 31;
#pragma unroll
        for (int i = 0; i < 4; i++) {
            const int mt = (wm0 >> 4) + i;
            af[i] = *(const uint4*)(Asf + ((ks * 8 + mt) * 32 + la) * 4);
        }
#pragma unroll
        for (int j = 0; j < 4; j++) {
            const int nt = (wn0 >> 3) + j;
            bf[j] = *(const uint2*)(Bsf + ((ks * 16 + nt) * 32 + lb) * 2);
        }
#pragma unroll
        for (int i = 0; i < 4; i++)
#pragma unroll
            for (int j = 0; j < 4; j++)
                mma_tf32(acc[i][j], af[i].x, af[i].y, af[i].z, af[i].w,
                         bf[j].x, bf[j].y);
    }

    // ---- epilogue: exp(v-20), row-sum partials, store ----
    float rsum[4][2];
#pragma unroll
    for (int i = 0; i < 4; i++) { rsum[i][0] = 0.f; rsum[i][1] = 0.f; }

    float* Ch = P + (long)blockIdx.z * T_LEN * T_LEN;
#pragma unroll
    for (int i = 0; i < 4; i++) {
#pragma unroll
        for (int j = 0; j < 4; j++) {
#pragma unroll
            for (int h2 = 0; h2 < 2; h2++) {
                const int m = gm0 + wm0 + i * 16 + gid + h2 * 8;
                const int n = gn0 + wn0 + j * 8 + tg * 2;
                float v0 = __expf(acc[i][j][h2 * 2 + 0] - 20.0f);
                float v1 = __expf(acc[i][j][h2 * 2 + 1] - 20.0f);
                rsum[i][h2] += v0 + v1;
                *(float2*)(Ch + (long)m * T_LEN + n) = make_float2(v0, v1);
            }
        }
    }
#pragma unroll
    for (int i = 0; i < 4; i++)
#pragma unroll
        for (int h2 = 0; h2 < 2; h2++)
#pragma unroll
            for (int o = 1; o < 4; o <<= 1)
                rsum[i][h2] += __shfl_xor_sync(0xffffffffu, rsum[i][h2], o);
    if (tg == 0) {
        const int wn = warp & 3;
#pragma unroll
        for (int i = 0; i < 4; i++)
#pragma unroll
            for (int h2 = 0; h2 < 2; h2++)
                srs[wn * 128 + wm0 + i * 16 + h2 * 8 + gid] = rsum[i][h2];
    }
    __syncthreads();
    if (tid < 128) {
        float s = srs[tid] + srs[128 + tid] + srs[256 + tid] + srs[384 + tid];
        rsp[((long)blockIdx.z * T_LEN + gm0 + tid) * NBX_SCORES + blockIdx.x] = s;
    }
}

// ---------------------------------------------------------------------------
// Generic double-buffered TF32 GEMM (unchanged from R3, minus EXPSUM use)
// ---------------------------------------------------------------------------
template<int BM, int BN, int BK, int WARPS_M, int WARPS_N,
         int EPI, bool EXPSUM, bool NORMA>
__global__ __launch_bounds__(WARPS_M*WARPS_N*32)
void gemm_k(const float* __restrict__ A, const float* __restrict__ B,
            const float* __restrict__ bias, float* __restrict__ C,
            const float* __restrict__ rowinv, float* __restrict__ rsp,
            int M, int N, int K, int ldc,
            long aH, long bH, long cH, long riH, float scale)
{
    constexpr int THREADS = WARPS_M*WARPS_N*32;
    constexpr int WM = BM/WARPS_M, WN = BN/WARPS_N;
    constexpr int MT = WM/16, NT = WN/8;
    constexpr int AV = BM*BK/(THREADS*4);
    constexpr int BV = BN*BK/(THREADS*4);

    A += blockIdx.z * aH;
    B += blockIdx.z * bH;
    C += blockIdx.z * cH;
    if (NORMA) rowinv += blockIdx.z * riH;

    __shared__ uint32_t As[2][BK][BM + 8];
    __shared__ uint32_t Bs[2][BK][BN + 8];

    const int tid  = threadIdx.x;
    const int warp = tid >> 5, lane = tid & 31;
    const int wm0 = (warp / WARPS_N) * WM;
    const int wn0 = (warp % WARPS_N) * WN;
    const int gid = lane >> 2, tg = lane & 3;
    const int gm0 = blockIdx.y * BM, gn0 = blockIdx.x * BN;

    int am[AV], ak[AV], bn[BV], bk[BV];
    float ainv[AV];
#pragma unroll
    for (int i = 0; i < AV; i++) {
        int idx = (tid + i*THREADS) * 4;
        am[i] = idx / BK; ak[i] = idx % BK;
        ainv[i] = NORMA ? rowinv[gm0 + am[i]] : 1.0f;
    }
#pragma unroll
    for (int i = 0; i < BV; i++) {
        int idx = (tid + i*THREADS) * 4;
        bn[i] = idx / BK; bk[i] = idx % BK;
    }

    float4 ra[AV], rb[BV];
    auto loadg = [&](int k0) {
#pragma unroll
        for (int i = 0; i < AV; i++)
            ra[i] = *(const float4*)(A + (long)(gm0 + am[i])*K + k0 + ak[i]);
#pragma unroll
        for (int i = 0; i < BV; i++)
            rb[i] = *(const float4*)(B + (long)(gn0 + bn[i])*K + k0 + bk[i]);
    };
    auto sts = [&](int buf) {
#pragma unroll
        for (int i = 0; i < AV; i++) {
            As[buf][ak[i]+0][am[i]] = f2tf32(ra[i].x * ainv[i]);
            As[buf][ak[i]+1][am[i]] = f2tf32(ra[i].y * ainv[i]);
            As[buf][ak[i]+2][am[i]] = f2tf32(ra[i].z * ainv[i]);
            As[buf][ak[i]+3][am[i]] = f2tf32(ra[i].w * ainv[i]);
        }
#pragma unroll
        for (int i = 0; i < BV; i++) {
            Bs[buf][bk[i]+0][bn[i]] = f2tf32(rb[i].x);
            Bs[buf][bk[i]+1][bn[i]] = f2tf32(rb[i].y);
            Bs[buf][bk[i]+2][bn[i]] = f2tf32(rb[i].z);
            Bs[buf][bk[i]+3][bn[i]] = f2tf32(rb[i].w);
        }
    };

    float acc[MT][NT][4];
#pragma unroll
    for (int i = 0; i < MT; i++)
#pragma unroll
        for (int j = 0; j < NT; j++)
#pragma unroll
            for (int q = 0; q < 4; q++) acc[i][j][q] = 0.0f;

    const int NI = K / BK;
    loadg(0);
    sts(0);
#pragma unroll 1
    for (int it = 0; it < NI; ++it) {
        __syncthreads();
        if (it + 1 < NI) loadg((it + 1) * BK);
        const int buf = it & 1;
#pragma unroll
        for (int ks = 0; ks < BK; ks += 8) {
            uint32_t af[MT][4], bf[NT][2];
#pragma unroll
            for (int i = 0; i < MT; i++) {
                int m = wm0 + i*16 + gid;
                af[i][0] = As[buf][ks + tg    ][m];
                af[i][1] = As[buf][ks + tg    ][m + 8];
                af[i][2] = As[buf][ks + tg + 4][m];
                af[i][3] = As[buf][ks + tg + 4][m + 8];
            }
#pragma unroll
            for (int j = 0; j < NT; j++) {
                int n = wn0 + j*8 + gid;
                bf[j][0] = Bs[buf][ks + tg    ][n];
                bf[j][1] = Bs[buf][ks + tg + 4][n];
            }
#pragma unroll
            for (int i = 0; i < MT; i++)
#pragma unroll
                for (int j = 0; j < NT; j++)
                    mma_tf32(acc[i][j], af[i][0], af[i][1], af[i][2], af[i][3],
                             bf[j][0], bf[j][1]);
        }
        if (it + 1 < NI) sts(buf ^ 1);
    }

#pragma unroll
    for (int i = 0; i < MT; i++) {
#pragma unroll
        for (int j = 0; j < NT; j++) {
#pragma unroll
            for (int h2 = 0; h2 < 2; h2++) {
                int m = gm0 + wm0 + i*16 + gid + h2*8;
                int n = gn0 + wn0 + j*8 + tg*2;
                float v0 = acc[i][j][h2*2 + 0];
                float v1 = acc[i][j][h2*2 + 1];
                if (bias) { v0 += bias[n]; v1 += bias[n+1]; }
                v0 *= scale; v1 *= scale;
                if (EPI == 0) {
                    *(float2*)(C + (long)m*ldc + n) = make_float2(v0, v1);
                } else if (EPI == 1) {          // [h][m][d]
                    int h = n >> 6, d = n & 63;
                    float* p = C + (long)h*M*HD + (long)m*HD + d;
                    p[0] = v0; p[1] = v1;
                } else {                        // [h][d][m]
                    int h = n >> 6, d = n & 63;
                    float* p = C + (long)h*HD*M + (long)d*M + m;
                    p[0] = v0; p[M] = v1;
                }
            }
        }
    }
}

// ---------------------------------------------------------------------------
__global__ __launch_bounds__(256) void invred_k(const float* __restrict__ part,
                                                float* __restrict__ inv)
{
    const int warp = threadIdx.x >> 5, lane = threadIdx.x & 31;
    const long row = (long)blockIdx.x * 8 + warp;
    float s = part[row * 32 + lane];
#pragma unroll
    for (int o = 16; o > 0; o >>= 1)
        s += __shfl_xor_sync(0xffffffffu, s, o);
    if (lane == 0) inv[row] = 1.0f / s;
}

// ---------------------------------------------------------------------------
__global__ __launch_bounds__(1024) void avg_k(const float* __restrict__ P,
                                              const float* __restrict__ inv,
                                              float* __restrict__ out)
{
    const int t = blockIdx.x, tid = threadIdx.x;
    const long TS4 = (long)T_LEN * T_LEN / 4;
    const float4* P4 = (const float4*)P + (long)t * (T_LEN/4) + tid;
    float4 acc = make_float4(0.f, 0.f, 0.f, 0.f);
#pragma unroll
    for (int h = 0; h < H_NUM; h++) {
        const float iv = inv[h * T_LEN + t] * (1.0f / H_NUM);
        float4 p = P4[(long)h * TS4];
        acc.x += p.x * iv; acc.y += p.y * iv;
        acc.z += p.z * iv; acc.w += p.w * iv;
    }
    ((float4*)(out + (long)t * T_LEN))[tid] = acc;
}

// ---------------------------------------------------------------------------
extern "C" void kernel_launch(void* const* d_in, const int* in_sizes, int n_in,
                              void* d_out, int out_size)
{
    const float* q_in = (const float*)d_in[0];
    const float* k_in = (const float*)d_in[1];
    const float* v_in = (const float*)d_in[2];
    const float* w    = (const float*)d_in[3];
    const float* b    = (const float*)d_in[4];
    const float* ow   = (const float*)d_in[5];
    const float* ob   = (const float*)d_in[6];
    float* out = (float*)d_out;

    float *Q, *K, *Vt, *P, *CTX, *RSP, *INV;
    cudaGetSymbolAddress((void**)&Q,   g_Q);
    cudaGetSymbolAddress((void**)&K,   g_K);
    cudaGetSymbolAddress((void**)&Vt,  g_Vt);
    cudaGetSymbolAddress((void**)&P,   g_P);
    cudaGetSymbolAddress((void**)&CTX, g_CTX);
    cudaGetSymbolAddress((void**)&RSP, g_RSP);
    cudaGetSymbolAddress((void**)&INV, g_INV);

    const int T = T_LEN, E = E_DIM, H = H_NUM;
    const long EE = (long)E * E;
    dim3 blk(256);

    // QKV projections
    gemm_k<128,128,16,2,4,1,false,false><<<dim3(E/128, T/128, 1), blk>>>(
        q_in, w,        b,       Q,  nullptr, nullptr, T, E, E, 0, 0,0,0,0, 0.125f);
    gemm_k<128,128,16,2,4,1,false,false><<<dim3(E/128, T/128, 1), blk>>>(
        k_in, w + EE,   b + E,   K,  nullptr, nullptr, T, E, E, 0, 0,0,0,0, 1.0f);
    gemm_k<128,128,16,2,4,2,false,false><<<dim3(E/128, T/128, 1), blk>>>(
        v_in, w + 2*EE, b + 2*E, Vt, nullptr, nullptr, T, E, E, 0, 0,0,0,0, 1.0f);

    // scores + exp + partial row sums (specialized fragment-major kernel)
    static const int SCORES_SMEM = (8*8*32*4 + 8*16*32*2) * 4 + 4*128*4;
    cudaFuncSetAttribute(scores_k, cudaFuncAttributeMaxDynamicSharedMemorySize,
                         SCORES_SMEM);
    scores_k<<<dim3(T/128, T/128, H), blk, SCORES_SMEM>>>(Q, K, P, RSP);

    // row-sum reduce -> inv
    invred_k<<<(H*T)/8, 256>>>(RSP, INV);

    // head-average -> second half of d_out
    avg_k<<<T, 1024>>>(P, INV, out + (long)T * E);

    // ctx: CTX[:, h*64:(h+1)*64] = (P[h] * inv) @ Vt[h]^T
    gemm_k<128,64,16,4,2,0,false,true><<<dim3(1, T/128, H), blk>>>(
        P, Vt, nullptr, CTX, INV, nullptr, T, HD, T, E,
        (long)T*T, (long)HD*T, 64, T, 1.0f);

    // out projection
    gemm_k<128,128,16,2,4,0,false,false><<<dim3(E/128, T/128, 1), blk>>>(
        CTX, ow, ob, out, nullptr, nullptr, T, E, E, E, 0,0,0,0, 1.0f);
}

// round 5
// speedup vs baseline: 2.5242x; 1.0654x over previous
#include <cuda_runtime.h>
#include <cuda_fp16.h>
#include <cstdint>

#define T_LEN 4096
#define E_DIM 1024
#define H_NUM 16
#define HD    64
#define NBX_SCORES 32   // gridDim.x of scores kernel (T/128)

// Scratch (allocation-free rule: __device__ globals)
__device__ float  g_Q  [(long)H_NUM * T_LEN * HD];    // [h][t][d]
__device__ float  g_K  [(long)H_NUM * T_LEN * HD];    // [h][t][d]
__device__ float  g_Vt [(long)H_NUM * HD * T_LEN];    // [h][d][t]
__device__ __half g_P  [(long)H_NUM * T_LEN * T_LEN]; // [h][t][s] scaled exp, fp16
__device__ float  g_CTX[(long)T_LEN * E_DIM];         // [t][e]
__device__ float  g_RSP[(long)H_NUM * T_LEN * NBX_SCORES]; // partial row sums
__device__ float  g_INV[(long)H_NUM * T_LEN];         // 1/rowsum (of scaled exps)

__device__ __forceinline__ uint32_t f2tf32(float x) {
    uint32_t r;
    asm("cvt.rna.tf32.f32 %0, %1;" : "=r"(r) : "f"(x));
    return r;
}

__device__ __forceinline__ float ex2(float x) {
    float r;
    asm("ex2.approx.f32 %0, %1;" : "=f"(r) : "f"(x));
    return r;
}

__device__ __forceinline__ void mma_tf32(float c[4],
    uint32_t a0, uint32_t a1, uint32_t a2, uint32_t a3,
    uint32_t b0, uint32_t b1)
{
    asm volatile(
        "mma.sync.aligned.m16n8k8.row.col.f32.tf32.tf32.f32 "
        "{%0,%1,%2,%3}, {%4,%5,%6,%7}, {%8,%9}, {%0,%1,%2,%3};"
        : "+f"(c[0]), "+f"(c[1]), "+f"(c[2]), "+f"(c[3])
        : "r"(a0), "r"(a1), "r"(a2), "r"(a3), "r"(b0), "r"(b1));
}

#define LOG2E 1.4426950408889634f
#define PSHIFT 2.0f   // p = 2^(s*log2e + 2): fp16-safe for s in [-11, +9.7]

// ===========================================================================
// Scores: P[h] tile = fp16( 2^(QK^T*log2e + 2) ), partial row sums (fp32).
// Fragment-major one-shot K=64 (see R4). 256 thr, 8 warps, tile 128x128.
// ===========================================================================
__global__ __launch_bounds__(256, 2)
void scores_k(const float* __restrict__ Q, const float* __restrict__ Kp,
              __half* __restrict__ P, float* __restrict__ rsp)
{
    extern __shared__ uint32_t smem[];
    uint32_t* Asf = smem;                 // 8*8*32*4  u32
    uint32_t* Bsf = smem + 8192;          // 8*16*32*2 u32
    float*    srs = (float*)(smem + 16384); // 4*128 floats

    const int tid  = threadIdx.x;
    const int warp = tid >> 5, lane = tid & 31;
    const int gid = lane >> 2, tg = lane & 3;
    const int wm0 = (warp >> 2) * 64;
    const int wn0 = (warp & 3) * 32;
    const int gm0 = blockIdx.y * 128, gn0 = blockIdx.x * 128;

    const float* Ah = Q  + (long)blockIdx.z * T_LEN * HD + (long)gm0 * HD;
    const float* Bh = Kp + (long)blockIdx.z * T_LEN * HD + (long)gn0 * HD;

#pragma unroll
    for (int i = 0; i < 8; i++) {
        const int idx = (tid + i * 256) * 4;
        const int m = idx >> 6, k = idx & 63;
        const int k8 = k >> 3, khi = (k >> 2) & 1;
        float4 t = *(const float4*)(Ah + m * 64 + k);
        const int r = m & 15, mt = m >> 4;
        const int rega = (r >> 3) + 2 * khi;
        const int lbase = (r & 7) * 4;
        uint32_t* dst = Asf + ((k8 * 8 + mt) * 32) * 4 + rega;
        dst[(((lbase + 0) + k8) & 31) * 4] = f2tf32(t.x);
        dst[(((lbase + 1) + k8) & 31) * 4] = f2tf32(t.y);
        dst[(((lbase + 2) + k8) & 31) * 4] = f2tf32(t.z);
        dst[(((lbase + 3) + k8) & 31) * 4] = f2tf32(t.w);
    }
#pragma unroll
    for (int i = 0; i < 8; i++) {
        const int idx = (tid + i * 256) * 4;
        const int n = idx >> 6, k = idx & 63;
        const int k8 = k >> 3, khi = (k >> 2) & 1;
        float4 t = *(const float4*)(Bh + n * 64 + k);
        const int nt = n >> 3;
        const int lbase = (n & 7) * 4;
        uint32_t* dst = Bsf + ((k8 * 16 + nt) * 32) * 2 + khi;
        dst[(((lbase + 0) + 2 * k8) & 31) * 2] = f2tf32(t.x);
        dst[(((lbase + 1) + 2 * k8) & 31) * 2] = f2tf32(t.y);
        dst[(((lbase + 2) + 2 * k8) & 31) * 2] = f2tf32(t.z);
        dst[(((lbase + 3) + 2 * k8) & 31) * 2] = f2tf32(t.w);
    }
    __syncthreads();

    float acc[4][4][4];
#pragma unroll
    for (int i = 0; i < 4; i++)
#pragma unroll
        for (int j = 0; j < 4; j++)
#pragma unroll
            for (int q = 0; q < 4; q++) acc[i][j][q] = 0.0f;

#pragma unroll
    for (int ks = 0; ks < 8; ks++) {
        uint4 af[4];
        uint2 bf[4];
        const int la = (lane + ks) & 31;
        const int lb = (lane + 2 * ks) & 31;
#pragma unroll
        for (int i = 0; i < 4; i++) {
            const int mt = (wm0 >> 4) + i;
            af[i] = *(const uint4*)(Asf + ((ks * 8 + mt) * 32 + la) * 4);
        }
#pragma unroll
        for (int j = 0; j < 4; j++) {
            const int nt = (wn0 >> 3) + j;
            bf[j] = *(const uint2*)(Bsf + ((ks * 16 + nt) * 32 + lb) * 2);
        }
#pragma unroll
        for (int i = 0; i < 4; i++)
#pragma unroll
            for (int j = 0; j < 4; j++)
                mma_tf32(acc[i][j], af[i].x, af[i].y, af[i].z, af[i].w,
                         bf[j].x, bf[j].y);
    }

    // ---- epilogue: p = 2^(s*log2e + 2) in fp16, fp32 row-sum partials ----
    float rsum[4][2];
#pragma unroll
    for (int i = 0; i < 4; i++) { rsum[i][0] = 0.f; rsum[i][1] = 0.f; }

    __half* Ch = P + (long)blockIdx.z * T_LEN * T_LEN;
#pragma unroll
    for (int i = 0; i < 4; i++) {
#pragma unroll
        for (int j = 0; j < 4; j++) {
#pragma unroll
            for (int h2 = 0; h2 < 2; h2++) {
                const int m = gm0 + wm0 + i * 16 + gid + h2 * 8;
                const int n = gn0 + wn0 + j * 8 + tg * 2;
                float v0 = ex2(fmaf(acc[i][j][h2 * 2 + 0], LOG2E, PSHIFT));
                float v1 = ex2(fmaf(acc[i][j][h2 * 2 + 1], LOG2E, PSHIFT));
                rsum[i][h2] += v0 + v1;
                *(__half2*)(Ch + (long)m * T_LEN + n) = __floats2half2_rn(v0, v1);
            }
        }
    }
#pragma unroll
    for (int i = 0; i < 4; i++)
#pragma unroll
        for (int h2 = 0; h2 < 2; h2++)
#pragma unroll
            for (int o = 1; o < 4; o <<= 1)
                rsum[i][h2] += __shfl_xor_sync(0xffffffffu, rsum[i][h2], o);
    if (tg == 0) {
        const int wn = warp & 3;
#pragma unroll
        for (int i = 0; i < 4; i++)
#pragma unroll
            for (int h2 = 0; h2 < 2; h2++)
                srs[wn * 128 + wm0 + i * 16 + h2 * 8 + gid] = rsum[i][h2];
    }
    __syncthreads();
    if (tid < 128) {
        float s = srs[tid] + srs[128 + tid] + srs[256 + tid] + srs[384 + tid];
        rsp[((long)blockIdx.z * T_LEN + gm0 + tid) * NBX_SCORES + blockIdx.x] = s;
    }
}

// ---------------------------------------------------------------------------
// Generic double-buffered TF32 GEMM. AHALF: A is fp16 (converted on load).
// ---------------------------------------------------------------------------
template<int BM, int BN, int BK, int WARPS_M, int WARPS_N,
         int EPI, bool NORMA, bool AHALF>
__global__ __launch_bounds__(WARPS_M*WARPS_N*32)
void gemm_k(const void* __restrict__ Av, const float* __restrict__ B,
            const float* __restrict__ bias, float* __restrict__ C,
            const float* __restrict__ rowinv,
            int M, int N, int K, int ldc,
            long aH, long bH, long cH, long riH, float scale)
{
    constexpr int THREADS = WARPS_M*WARPS_N*32;
    constexpr int WM = BM/WARPS_M, WN = BN/WARPS_N;
    constexpr int MT = WM/16, NT = WN/8;
    constexpr int AV = BM*BK/(THREADS*4);
    constexpr int BV = BN*BK/(THREADS*4);

    const float*  Af = (const float*)Av  + (AHALF ? 0 : blockIdx.z * aH);
    const __half* Ah = (const __half*)Av + (AHALF ? blockIdx.z * aH : 0);
    B += blockIdx.z * bH;
    C += blockIdx.z * cH;
    if (NORMA) rowinv += blockIdx.z * riH;

    __shared__ uint32_t As[2][BK][BM + 8];
    __shared__ uint32_t Bs[2][BK][BN + 8];

    const int tid  = threadIdx.x;
    const int warp = tid >> 5, lane = tid & 31;
    const int wm0 = (warp / WARPS_N) * WM;
    const int wn0 = (warp % WARPS_N) * WN;
    const int gid = lane >> 2, tg = lane & 3;
    const int gm0 = blockIdx.y * BM, gn0 = blockIdx.x * BN;

    int am[AV], ak[AV], bn[BV], bk[BV];
    float ainv[AV];
#pragma unroll
    for (int i = 0; i < AV; i++) {
        int idx = (tid + i*THREADS) * 4;
        am[i] = idx / BK; ak[i] = idx % BK;
        ainv[i] = NORMA ? rowinv[gm0 + am[i]] : 1.0f;
    }
#pragma unroll
    for (int i = 0; i < BV; i++) {
        int idx = (tid + i*THREADS) * 4;
        bn[i] = idx / BK; bk[i] = idx % BK;
    }

    float4 ra[AV], rb[BV];
    auto loadg = [&](int k0) {
#pragma unroll
        for (int i = 0; i < AV; i++) {
            if (AHALF) {
                uint2 u = *(const uint2*)(Ah + (long)(gm0 + am[i])*K + k0 + ak[i]);
                float2 lo = __half22float2(*(__half2*)&u.x);
                float2 hi = __half22float2(*(__half2*)&u.y);
                ra[i] = make_float4(lo.x, lo.y, hi.x, hi.y);
            } else {
                ra[i] = *(const float4*)(Af + (long)(gm0 + am[i])*K + k0 + ak[i]);
            }
        }
#pragma unroll
        for (int i = 0; i < BV; i++)
            rb[i] = *(const float4*)(B + (long)(gn0 + bn[i])*K + k0 + bk[i]);
    };
    auto sts = [&](int buf) {
#pragma unroll
        for (int i = 0; i < AV; i++) {
            As[buf][ak[i]+0][am[i]] = f2tf32(ra[i].x * ainv[i]);
            As[buf][ak[i]+1][am[i]] = f2tf32(ra[i].y * ainv[i]);
            As[buf][ak[i]+2][am[i]] = f2tf32(ra[i].z * ainv[i]);
            As[buf][ak[i]+3][am[i]] = f2tf32(ra[i].w * ainv[i]);
        }
#pragma unroll
        for (int i = 0; i < BV; i++) {
            Bs[buf][bk[i]+0][bn[i]] = f2tf32(rb[i].x);
            Bs[buf][bk[i]+1][bn[i]] = f2tf32(rb[i].y);
            Bs[buf][bk[i]+2][bn[i]] = f2tf32(rb[i].z);
            Bs[buf][bk[i]+3][bn[i]] = f2tf32(rb[i].w);
        }
    };

    float acc[MT][NT][4];
#pragma unroll
    for (int i = 0; i < MT; i++)
#pragma unroll
        for (int j = 0; j < NT; j++)
#pragma unroll
            for (int q = 0; q < 4; q++) acc[i][j][q] = 0.0f;

    const int NI = K / BK;
    loadg(0);
    sts(0);
#pragma unroll 1
    for (int it = 0; it < NI; ++it) {
        __syncthreads();
        if (it + 1 < NI) loadg((it + 1) * BK);
        const int buf = it & 1;
#pragma unroll
        for (int ks = 0; ks < BK; ks += 8) {
            uint32_t af[MT][4], bf[NT][2];
#pragma unroll
            for (int i = 0; i < MT; i++) {
                int m = wm0 + i*16 + gid;
                af[i][0] = As[buf][ks + tg    ][m];
                af[i][1] = As[buf][ks + tg    ][m + 8];
                af[i][2] = As[buf][ks + tg + 4][m];
                af[i][3] = As[buf][ks + tg + 4][m + 8];
            }
#pragma unroll
            for (int j = 0; j < NT; j++) {
                int n = wn0 + j*8 + gid;
                bf[j][0] = Bs[buf][ks + tg    ][n];
                bf[j][1] = Bs[buf][ks + tg + 4][n];
            }
#pragma unroll
            for (int i = 0; i < MT; i++)
#pragma unroll
                for (int j = 0; j < NT; j++)
                    mma_tf32(acc[i][j], af[i][0], af[i][1], af[i][2], af[i][3],
                             bf[j][0], bf[j][1]);
        }
        if (it + 1 < NI) sts(buf ^ 1);
    }

#pragma unroll
    for (int i = 0; i < MT; i++) {
#pragma unroll
        for (int j = 0; j < NT; j++) {
#pragma unroll
            for (int h2 = 0; h2 < 2; h2++) {
                int m = gm0 + wm0 + i*16 + gid + h2*8;
                int n = gn0 + wn0 + j*8 + tg*2;
                float v0 = acc[i][j][h2*2 + 0];
                float v1 = acc[i][j][h2*2 + 1];
                if (bias) { v0 += bias[n]; v1 += bias[n+1]; }
                v0 *= scale; v1 *= scale;
                if (EPI == 0) {
                    *(float2*)(C + (long)m*ldc + n) = make_float2(v0, v1);
                } else if (EPI == 1) {          // [h][m][d]
                    int h = n >> 6, d = n & 63;
                    float* p = C + (long)h*M*HD + (long)m*HD + d;
                    p[0] = v0; p[1] = v1;
                } else {                        // [h][d][m]
                    int h = n >> 6, d = n & 63;
                    float* p = C + (long)h*HD*M + (long)d*M + m;
                    p[0] = v0; p[M] = v1;
                }
            }
        }
    }
}

// ---------------------------------------------------------------------------
__global__ __launch_bounds__(256) void invred_k(const float* __restrict__ part,
                                                float* __restrict__ inv)
{
    const int warp = threadIdx.x >> 5, lane = threadIdx.x & 31;
    const long row = (long)blockIdx.x * 8 + warp;
    float s = part[row * 32 + lane];
#pragma unroll
    for (int o = 16; o > 0; o >>= 1)
        s += __shfl_xor_sync(0xffffffffu, s, o);
    if (lane == 0) inv[row] = 1.0f / s;
}

// ---------------------------------------------------------------------------
// avg[t][s] = (1/H) * sum_h P16[h][t][s] * inv[h][t]
// 1024 threads; each handles 4 halfs (uint2) per head.
// ---------------------------------------------------------------------------
__global__ __launch_bounds__(1024) void avg_k(const __half* __restrict__ P,
                                              const float* __restrict__ inv,
                                              float* __restrict__ out)
{
    const int t = blockIdx.x, tid = threadIdx.x;
    const long TS = (long)T_LEN * T_LEN;
    const __half* base = P + (long)t * T_LEN + tid * 4;
    float4 acc = make_float4(0.f, 0.f, 0.f, 0.f);
#pragma unroll
    for (int h = 0; h < H_NUM; h++) {
        const float iv = inv[h * T_LEN + t] * (1.0f / H_NUM);
        uint2 u = *(const uint2*)(base + (long)h * TS);
        float2 lo = __half22float2(*(__half2*)&u.x);
        float2 hi = __half22float2(*(__half2*)&u.y);
        acc.x += lo.x * iv; acc.y += lo.y * iv;
        acc.z += hi.x * iv; acc.w += hi.y * iv;
    }
    ((float4*)(out + (long)t * T_LEN))[tid] = acc;
}

// ---------------------------------------------------------------------------
extern "C" void kernel_launch(void* const* d_in, const int* in_sizes, int n_in,
                              void* d_out, int out_size)
{
    const float* q_in = (const float*)d_in[0];
    const float* k_in = (const float*)d_in[1];
    const float* v_in = (const float*)d_in[2];
    const float* w    = (const float*)d_in[3];
    const float* b    = (const float*)d_in[4];
    const float* ow   = (const float*)d_in[5];
    const float* ob   = (const float*)d_in[6];
    float* out = (float*)d_out;

    float *Q, *K, *Vt, *CTX, *RSP, *INV;
    __half *P;
    cudaGetSymbolAddress((void**)&Q,   g_Q);
    cudaGetSymbolAddress((void**)&K,   g_K);
    cudaGetSymbolAddress((void**)&Vt,  g_Vt);
    cudaGetSymbolAddress((void**)&P,   g_P);
    cudaGetSymbolAddress((void**)&CTX, g_CTX);
    cudaGetSymbolAddress((void**)&RSP, g_RSP);
    cudaGetSymbolAddress((void**)&INV, g_INV);

    const int T = T_LEN, E = E_DIM, H = H_NUM;
    const long EE = (long)E * E;
    dim3 blk(256);

    // QKV projections
    gemm_k<128,128,16,2,4,1,false,false><<<dim3(E/128, T/128, 1), blk>>>(
        q_in, w,        b,       Q,  nullptr, T, E, E, 0, 0,0,0,0, 0.125f);
    gemm_k<128,128,16,2,4,1,false,false><<<dim3(E/128, T/128, 1), blk>>>(
        k_in, w + EE,   b + E,   K,  nullptr, T, E, E, 0, 0,0,0,0, 1.0f);
    gemm_k<128,128,16,2,4,2,false,false><<<dim3(E/128, T/128, 1), blk>>>(
        v_in, w + 2*EE, b + 2*E, Vt, nullptr, T, E, E, 0, 0,0,0,0, 1.0f);

    // scores -> fp16 P + partial row sums
    static const int SCORES_SMEM = (8*8*32*4 + 8*16*32*2) * 4 + 4*128*4;
    cudaFuncSetAttribute(scores_k, cudaFuncAttributeMaxDynamicSharedMemorySize,
                         SCORES_SMEM);
    scores_k<<<dim3(T/128, T/128, H), blk, SCORES_SMEM>>>(Q, K, P, RSP);

    // row-sum reduce -> inv
    invred_k<<<(H*T)/8, 256>>>(RSP, INV);

    // head-average -> second half of d_out
    avg_k<<<T, 1024>>>(P, INV, out + (long)T * E);

    // ctx: CTX[:, h*64:(h+1)*64] = (P16[h] * inv) @ Vt[h]^T
    gemm_k<128,64,16,4,2,0,true,true><<<dim3(1, T/128, H), blk>>>(
        P, Vt, nullptr, CTX, INV, T, HD, T, E,
        (long)T*T, (long)HD*T, 64, T, 1.0f);

    // out projection
    gemm_k<128,128,16,2,4,0,false,false><<<dim3(E/128, T/128, 1), blk>>>(
        CTX, ow, ob, out, nullptr, T, E, E, E, 0,0,0,0, 1.0f);
}

// round 7
// speedup vs baseline: 4.5545x; 1.8043x over previous
#include <cuda_runtime.h>
#include <cuda_fp16.h>
#include <cstdint>

#define T_LEN 4096
#define E_DIM 1024
#define H_NUM 16
#define HD    64
#define NBX_SCORES 32   // gridDim.x of scores kernel (T/128)

// Scratch (allocation-free rule: __device__ globals)
__device__ __half g_Q  [(long)H_NUM * T_LEN * HD];    // [h][t][d] fp16
__device__ __half g_K  [(long)H_NUM * T_LEN * HD];    // [h][t][d] fp16
__device__ __half g_Vt [(long)H_NUM * HD * T_LEN];    // [h][d][t] fp16
__device__ __half g_P  [(long)H_NUM * T_LEN * T_LEN]; // [h][t][s] scaled exp fp16
__device__ __half g_CTX[(long)T_LEN * E_DIM];         // [t][e] fp16
__device__ float  g_RSP[(long)H_NUM * T_LEN * NBX_SCORES];
__device__ float  g_INV[(long)H_NUM * T_LEN];         // 1/rowsum

__device__ __forceinline__ float ex2(float x) {
    float r;
    asm("ex2.approx.f32 %0, %1;" : "=f"(r) : "f"(x));
    return r;
}

// fp16 MMA, fp32 accum: D = A(16x16,row) * B(16x8,col) + D
__device__ __forceinline__ void mma_f16(float c[4],
    uint32_t a0, uint32_t a1, uint32_t a2, uint32_t a3,
    uint32_t b0, uint32_t b1)
{
    asm volatile(
        "mma.sync.aligned.m16n8k16.row.col.f32.f16.f16.f32 "
        "{%0,%1,%2,%3}, {%4,%5,%6,%7}, {%8,%9}, {%0,%1,%2,%3};"
        : "+f"(c[0]), "+f"(c[1]), "+f"(c[2]), "+f"(c[3])
        : "r"(a0), "r"(a1), "r"(a2), "r"(a3), "r"(b0), "r"(b1));
}

#define LOG2E 1.4426950408889634f
#define PSHIFT 2.0f   // p = 2^(s*log2e + 2)

// ===========================================================================
// Scores: P[h] = fp16( 2^(QK^T*log2e + 2) ), fp32 partial row sums.
// Q,K fp16 [h][t][64]. One-shot K=64, K-major smem (stride 72 halfs).
// 256 thr, 8 warps (2x4), warp tile 64x32, block tile 128x128.
// ===========================================================================
__global__ __launch_bounds__(256, 2)
void scores_k(const __half* __restrict__ Q, const __half* __restrict__ Kp,
              __half* __restrict__ P, float* __restrict__ rsp)
{
    __shared__ __half As[128][72];
    __shared__ __half Bs[128][72];
    __shared__ float  srs[512];

    const int tid  = threadIdx.x;
    const int warp = tid >> 5, lane = tid & 31;
    const int gid = lane >> 2, tg = lane & 3;
    const int wm0 = (warp >> 2) * 64;
    const int wn0 = (warp & 3) * 32;
    const int gm0 = blockIdx.y * 128, gn0 = blockIdx.x * 128;

    const __half* Ah = Q  + (long)blockIdx.z * T_LEN * HD + (long)gm0 * HD;
    const __half* Bh = Kp + (long)blockIdx.z * T_LEN * HD + (long)gn0 * HD;

    // A: 128x64 halfs = 8192; 256 thr * 8 halfs = 2048/iter -> 4 iters. Same B.
#pragma unroll
    for (int i = 0; i < 4; i++) {
        const int idx = (tid + i * 256) * 8;
        const int m = idx >> 6, k = idx & 63;
        *(uint4*)&As[m][k] = *(const uint4*)(Ah + (long)m * 64 + k);
    }
#pragma unroll
    for (int i = 0; i < 4; i++) {
        const int idx = (tid + i * 256) * 8;
        const int m = idx >> 6, k = idx & 63;
        *(uint4*)&Bs[m][k] = *(const uint4*)(Bh + (long)m * 64 + k);
    }
    __syncthreads();

    float acc[4][4][4];
#pragma unroll
    for (int i = 0; i < 4; i++)
#pragma unroll
        for (int j = 0; j < 4; j++)
#pragma unroll
            for (int q = 0; q < 4; q++) acc[i][j][q] = 0.0f;

#pragma unroll
    for (int ks = 0; ks < 64; ks += 16) {
        uint32_t af[4][4], bf[4][2];
#pragma unroll
        for (int i = 0; i < 4; i++) {
            const int m = wm0 + i * 16 + gid;
            af[i][0] = *(const uint32_t*)&As[m    ][ks + 2*tg];
            af[i][1] = *(const uint32_t*)&As[m + 8][ks + 2*tg];
            af[i][2] = *(const uint32_t*)&As[m    ][ks + 2*tg + 8];
            af[i][3] = *(const uint32_t*)&As[m + 8][ks + 2*tg + 8];
        }
#pragma unroll
        for (int j = 0; j < 4; j++) {
            const int n = wn0 + j * 8 + gid;
            bf[j][0] = *(const uint32_t*)&Bs[n][ks + 2*tg];
            bf[j][1] = *(const uint32_t*)&Bs[n][ks + 2*tg + 8];
        }
#pragma unroll
        for (int i = 0; i < 4; i++)
#pragma unroll
            for (int j = 0; j < 4; j++)
                mma_f16(acc[i][j], af[i][0], af[i][1], af[i][2], af[i][3],
                        bf[j][0], bf[j][1]);
    }

    // epilogue: p = 2^(s*log2e + 2) fp16, fp32 row-sum partials
    float rsum[4][2];
#pragma unroll
    for (int i = 0; i < 4; i++) { rsum[i][0] = 0.f; rsum[i][1] = 0.f; }

    __half* Ch = P + (long)blockIdx.z * T_LEN * T_LEN;
#pragma unroll
    for (int i = 0; i < 4; i++) {
#pragma unroll
        for (int j = 0; j < 4; j++) {
#pragma unroll
            for (int h2 = 0; h2 < 2; h2++) {
                const int m = gm0 + wm0 + i * 16 + gid + h2 * 8;
                const int n = gn0 + wn0 + j * 8 + tg * 2;
                float v0 = ex2(fmaf(acc[i][j][h2 * 2 + 0], LOG2E, PSHIFT));
                float v1 = ex2(fmaf(acc[i][j][h2 * 2 + 1], LOG2E, PSHIFT));
                rsum[i][h2] += v0 + v1;
                *(__half2*)(Ch + (long)m * T_LEN + n) = __floats2half2_rn(v0, v1);
            }
        }
    }
#pragma unroll
    for (int i = 0; i < 4; i++)
#pragma unroll
        for (int h2 = 0; h2 < 2; h2++)
#pragma unroll
            for (int o = 1; o < 4; o <<= 1)
                rsum[i][h2] += __shfl_xor_sync(0xffffffffu, rsum[i][h2], o);
    if (tg == 0) {
        const int wn = warp & 3;
#pragma unroll
        for (int i = 0; i < 4; i++)
#pragma unroll
            for (int h2 = 0; h2 < 2; h2++)
                srs[wn * 128 + wm0 + i * 16 + h2 * 8 + gid] = rsum[i][h2];
    }
    __syncthreads();
    if (tid < 128) {
        float s = srs[tid] + srs[128 + tid] + srs[256 + tid] + srs[384 + tid];
        rsp[((long)blockIdx.z * T_LEN + gm0 + tid) * NBX_SCORES + blockIdx.x] = s;
    }
}

// ===========================================================================
// Generic fp16-MMA GEMM, double-buffered, BK=32 (halfs).
//   A (M,K) rm; B (N,K) rm. AH/BH: global operand already fp16 (else fp32,
//   converted on load). CH: C stored fp16. NORMROW: scale row m by rowinv[m].
//   EPI 0: C[m*ldc+n]; 1: [h][m][d]; 2: [h][d][m]  (h=n>>6, d=n&63)
// ===========================================================================
template<int BM, int BN, int WARPS_M, int WARPS_N,
         int EPI, bool AH, bool BH, bool NORMROW, bool CH>
__global__ __launch_bounds__(WARPS_M*WARPS_N*32)
void gemm_k(const void* __restrict__ Av, const void* __restrict__ Bv,
            const float* __restrict__ bias, void* __restrict__ Cv,
            const float* __restrict__ rowinv,
            int M, int N, int K, int ldc,
            long aH, long bH, long cH, long riH, float scale)
{
    constexpr int THREADS = WARPS_M*WARPS_N*32;
    constexpr int BK = 32;
    constexpr int WM = BM/WARPS_M, WN = BN/WARPS_N;
    constexpr int MT = WM/16, NT = WN/8;

    const float*  Af  = (const float*) Av + (AH ? 0 : blockIdx.z * aH);
    const __half* Ahp = (const __half*)Av + (AH ? blockIdx.z * aH : 0);
    const float*  Bf  = (const float*) Bv + (BH ? 0 : blockIdx.z * bH);
    const __half* Bhp = (const __half*)Bv + (BH ? blockIdx.z * bH : 0);
    float*  Cf  = (float*) Cv + (CH ? 0 : blockIdx.z * cH);
    __half* Chp = (__half*)Cv + (CH ? blockIdx.z * cH : 0);
    if (NORMROW) rowinv += blockIdx.z * riH;

    __shared__ __half As[2][BM][40];
    __shared__ __half Bs[2][BN][40];

    const int tid  = threadIdx.x;
    const int warp = tid >> 5, lane = tid & 31;
    const int wm0 = (warp / WARPS_N) * WM;
    const int wn0 = (warp % WARPS_N) * WN;
    const int gid = lane >> 2, tg = lane & 3;
    const int gm0 = blockIdx.y * BM, gn0 = blockIdx.x * BN;

    constexpr int AC = AH ? BM*BK/(THREADS*8) : BM*BK/(THREADS*4);
    constexpr int BC = BH ? BN*BK/(THREADS*8) : BN*BK/(THREADS*4);
    int am[AC], ak[AC], bn[BC], bk[BC];
#pragma unroll
    for (int i = 0; i < AC; i++) {
        int idx = (tid + i*THREADS) * (AH ? 8 : 4);
        am[i] = idx / BK; ak[i] = idx % BK;
    }
#pragma unroll
    for (int i = 0; i < BC; i++) {
        int idx = (tid + i*THREADS) * (BH ? 8 : 4);
        bn[i] = idx / BK; bk[i] = idx % BK;
    }

    uint4  ra16[AC], rb16[BC];
    float4 ra32[AC], rb32[BC];
    auto loadg = [&](int k0) {
#pragma unroll
        for (int i = 0; i < AC; i++) {
            if (AH) ra16[i] = *(const uint4*)(Ahp + (long)(gm0 + am[i])*K + k0 + ak[i]);
            else    ra32[i] = *(const float4*)(Af + (long)(gm0 + am[i])*K + k0 + ak[i]);
        }
#pragma unroll
        for (int i = 0; i < BC; i++) {
            if (BH) rb16[i] = *(const uint4*)(Bhp + (long)(gn0 + bn[i])*K + k0 + bk[i]);
            else    rb32[i] = *(const float4*)(Bf + (long)(gn0 + bn[i])*K + k0 + bk[i]);
        }
    };
    auto sts = [&](int buf) {
#pragma unroll
        for (int i = 0; i < AC; i++) {
            if (AH) *(uint4*)&As[buf][am[i]][ak[i]] = ra16[i];
            else {
                __half2 lo = __floats2half2_rn(ra32[i].x, ra32[i].y);
                __half2 hi = __floats2half2_rn(ra32[i].z, ra32[i].w);
                *(__half2*)&As[buf][am[i]][ak[i]    ] = lo;
                *(__half2*)&As[buf][am[i]][ak[i] + 2] = hi;
            }
        }
#pragma unroll
        for (int i = 0; i < BC; i++) {
            if (BH) *(uint4*)&Bs[buf][bn[i]][bk[i]] = rb16[i];
            else {
                __half2 lo = __floats2half2_rn(rb32[i].x, rb32[i].y);
                __half2 hi = __floats2half2_rn(rb32[i].z, rb32[i].w);
                *(__half2*)&Bs[buf][bn[i]][bk[i]    ] = lo;
                *(__half2*)&Bs[buf][bn[i]][bk[i] + 2] = hi;
            }
        }
    };

    float acc[MT][NT][4];
#pragma unroll
    for (int i = 0; i < MT; i++)
#pragma unroll
        for (int j = 0; j < NT; j++)
#pragma unroll
            for (int q = 0; q < 4; q++) acc[i][j][q] = 0.0f;

    const int NI = K / BK;
    loadg(0);
    sts(0);
#pragma unroll 1
    for (int it = 0; it < NI; ++it) {
        __syncthreads();
        if (it + 1 < NI) loadg((it + 1) * BK);
        const int buf = it & 1;
#pragma unroll
        for (int ks = 0; ks < BK; ks += 16) {
            uint32_t af[MT][4], bf[NT][2];
#pragma unroll
            for (int i = 0; i < MT; i++) {
                int m = wm0 + i*16 + gid;
                af[i][0] = *(const uint32_t*)&As[buf][m    ][ks + 2*tg];
                af[i][1] = *(const uint32_t*)&As[buf][m + 8][ks + 2*tg];
                af[i][2] = *(const uint32_t*)&As[buf][m    ][ks + 2*tg + 8];
                af[i][3] = *(const uint32_t*)&As[buf][m + 8][ks + 2*tg + 8];
            }
#pragma unroll
            for (int j = 0; j < NT; j++) {
                int n = wn0 + j*8 + gid;
                bf[j][0] = *(const uint32_t*)&Bs[buf][n][ks + 2*tg];
                bf[j][1] = *(const uint32_t*)&Bs[buf][n][ks + 2*tg + 8];
            }
#pragma unroll
            for (int i = 0; i < MT; i++)
#pragma unroll
                for (int j = 0; j < NT; j++)
                    mma_f16(acc[i][j], af[i][0], af[i][1], af[i][2], af[i][3],
                            bf[j][0], bf[j][1]);
        }
        if (it + 1 < NI) sts(buf ^ 1);
    }

#pragma unroll
    for (int i = 0; i < MT; i++) {
#pragma unroll
        for (int j = 0; j < NT; j++) {
#pragma unroll
            for (int h2 = 0; h2 < 2; h2++) {
                int m = gm0 + wm0 + i*16 + gid + h2*8;
                int n = gn0 + wn0 + j*8 + tg*2;
                float v0 = acc[i][j][h2*2 + 0];
                float v1 = acc[i][j][h2*2 + 1];
                if (bias) { v0 += bias[n]; v1 += bias[n+1]; }
                float sc = NORMROW ? rowinv[m] : scale;
                v0 *= sc; v1 *= sc;
                if (EPI == 0) {
                    if (CH) *(__half2*)(Chp + (long)m*ldc + n) = __floats2half2_rn(v0, v1);
                    else    *(float2*)(Cf + (long)m*ldc + n) = make_float2(v0, v1);
                } else if (EPI == 1) {          // [h][m][d]
                    int h = n >> 6, d = n & 63;
                    *(__half2*)(Chp + (long)h*M*HD + (long)m*HD + d) =
                        __floats2half2_rn(v0, v1);
                } else {                        // [h][d][m]
                    int h = n >> 6, d = n & 63;
                    __half* p = Chp + (long)h*HD*M + (long)d*M + m;
                    p[0] = __float2half_rn(v0);
                    p[M] = __float2half_rn(v1);
                }
            }
        }
    }
}

// ---------------------------------------------------------------------------
__global__ __launch_bounds__(256) void invred_k(const float* __restrict__ part,
                                                float* __restrict__ inv)
{
    const int warp = threadIdx.x >> 5, lane = threadIdx.x & 31;
    const long row = (long)blockIdx.x * 8 + warp;
    float s = part[row * 32 + lane];
#pragma unroll
    for (int o = 16; o > 0; o >>= 1)
        s += __shfl_xor_sync(0xffffffffu, s, o);
    if (lane == 0) inv[row] = 1.0f / s;
}

// ---------------------------------------------------------------------------
__global__ __launch_bounds__(1024) void avg_k(const __half* __restrict__ P,
                                              const float* __restrict__ inv,
                                              float* __restrict__ out)
{
    const int t = blockIdx.x, tid = threadIdx.x;
    const long TS = (long)T_LEN * T_LEN;
    const __half* base = P + (long)t * T_LEN + tid * 4;
    float4 acc = make_float4(0.f, 0.f, 0.f, 0.f);
#pragma unroll
    for (int h = 0; h < H_NUM; h++) {
        const float iv = inv[h * T_LEN + t] * (1.0f / H_NUM);
        uint2 u = *(const uint2*)(base + (long)h * TS);
        float2 lo = __half22float2(*(__half2*)&u.x);
        float2 hi = __half22float2(*(__half2*)&u.y);
        acc.x += lo.x * iv; acc.y += lo.y * iv;
        acc.z += hi.x * iv; acc.w += hi.y * iv;
    }
    ((float4*)(out + (long)t * T_LEN))[tid] = acc;
}

// ---------------------------------------------------------------------------
extern "C" void kernel_launch(void* const* d_in, const int* in_sizes, int n_in,
                              void* d_out, int out_size)
{
    const float* q_in = (const float*)d_in[0];
    const float* k_in = (const float*)d_in[1];
    const float* v_in = (const float*)d_in[2];
    const float* w    = (const float*)d_in[3];
    const float* b    = (const float*)d_in[4];
    const float* ow   = (const float*)d_in[5];
    const float* ob   = (const float*)d_in[6];
    float* out = (float*)d_out;

    __half *Q, *K, *Vt, *P, *CTX;
    float *RSP, *INV;
    cudaGetSymbolAddress((void**)&Q,   g_Q);
    cudaGetSymbolAddress((void**)&K,   g_K);
    cudaGetSymbolAddress((void**)&Vt,  g_Vt);
    cudaGetSymbolAddress((void**)&P,   g_P);
    cudaGetSymbolAddress((void**)&CTX, g_CTX);
    cudaGetSymbolAddress((void**)&RSP, g_RSP);
    cudaGetSymbolAddress((void**)&INV, g_INV);

    const int T = T_LEN, E = E_DIM, H = H_NUM;
    const long EE = (long)E * E;
    dim3 blk(256);

    // QKV projections: fp32 in -> fp16 head-major out
    gemm_k<128,128,2,4,1,false,false,false,true><<<dim3(E/128, T/128, 1), blk>>>(
        q_in, w,        b,       Q,  nullptr, T, E, E, 0, 0,0,0,0, 0.125f);
    gemm_k<128,128,2,4,1,false,false,false,true><<<dim3(E/128, T/128, 1), blk>>>(
        k_in, w + EE,   b + E,   K,  nullptr, T, E, E, 0, 0,0,0,0, 1.0f);
    gemm_k<128,128,2,4,2,false,false,false,true><<<dim3(E/128, T/128, 1), blk>>>(
        v_in, w + 2*EE, b + 2*E, Vt, nullptr, T, E, E, 0, 0,0,0,0, 1.0f);

    // scores -> fp16 P + partial row sums
    scores_k<<<dim3(T/128, T/128, H), blk>>>(Q, K, P, RSP);

    // row-sum reduce -> inv
    invred_k<<<(H*T)/8, 256>>>(RSP, INV);

    // head-average -> second half of d_out
    avg_k<<<T, 1024>>>(P, INV, out + (long)T * E);

    // ctx: CTX[t, h*64+d] = inv[h][t] * (P16[h] @ Vt16[h]^T)   (fp16 out)
    gemm_k<128,64,4,2,0,true,true,true,true><<<dim3(1, T/128, H), blk>>>(
        P, Vt, nullptr, CTX, INV, T, HD, T, E,
        (long)T*T, (long)HD*T, 64, T, 1.0f);

    // out projection: fp16 CTX @ fp32 W^T + bias -> fp32 out
    gemm_k<128,128,2,4,0,true,false,false,false><<<dim3(E/128, T/128, 1), blk>>>(
        CTX, ow, ob, out, nullptr, T, E, E, E, 0,0,0,0, 1.0f);
}

// round 8
// speedup vs baseline: 4.5902x; 1.0078x over previous
#include <cuda_runtime.h>
#include <cuda_fp16.h>
#include <cstdint>

#define T_LEN 4096
#define E_DIM 1024
#define H_NUM 16
#define HD    64
#define NBX_SCORES 32   // gridDim.x of scores kernel (T/128)

// Scratch (allocation-free rule: __device__ globals)
__device__ __half g_Q  [(long)H_NUM * T_LEN * HD];    // [h][t][d] fp16
__device__ __half g_K  [(long)H_NUM * T_LEN * HD];    // [h][t][d] fp16
__device__ __half g_Vt [(long)H_NUM * HD * T_LEN];    // [h][d][t] fp16
__device__ __half g_P  [(long)H_NUM * T_LEN * T_LEN]; // [h][t][s] scaled exp fp16
__device__ __half g_CTX[(long)T_LEN * E_DIM];         // [t][e] fp16
__device__ float  g_RSP[(long)H_NUM * T_LEN * NBX_SCORES];
__device__ float  g_INV[(long)H_NUM * T_LEN];         // 1/rowsum

__device__ __forceinline__ float ex2(float x) {
    float r;
    asm("ex2.approx.f32 %0, %1;" : "=f"(r) : "f"(x));
    return r;
}

__device__ __forceinline__ uint32_t smem_u32(const void* p) {
    return (uint32_t)__cvta_generic_to_shared(p);
}

__device__ __forceinline__ void ldsm_x4(uint32_t r[4], uint32_t addr) {
    asm volatile("ldmatrix.sync.aligned.m8n8.x4.shared.b16 {%0,%1,%2,%3}, [%4];"
        : "=r"(r[0]), "=r"(r[1]), "=r"(r[2]), "=r"(r[3]) : "r"(addr));
}

// fp16 MMA, fp32 accum: D = A(16x16,row) * B(16x8,col) + D
__device__ __forceinline__ void mma_f16(float c[4],
    uint32_t a0, uint32_t a1, uint32_t a2, uint32_t a3,
    uint32_t b0, uint32_t b1)
{
    asm volatile(
        "mma.sync.aligned.m16n8k16.row.col.f32.f16.f16.f32 "
        "{%0,%1,%2,%3}, {%4,%5,%6,%7}, {%8,%9}, {%0,%1,%2,%3};"
        : "+f"(c[0]), "+f"(c[1]), "+f"(c[2]), "+f"(c[3])
        : "r"(a0), "r"(a1), "r"(a2), "r"(a3), "r"(b0), "r"(b1));
}

#define LOG2E 1.4426950408889634f
#define PSHIFT 2.0f   // p = 2^(s*log2e + 2)

// ===========================================================================
// Scores: P[h] = fp16( 2^(QK^T*log2e + 2) ), fp32 partial row sums.
// One-shot K=64, K-major smem stride 72 (conflict-free LDSM).
// 256 thr, 8 warps (2x4), warp tile 64x32, block tile 128x128.
// ===========================================================================
__global__ __launch_bounds__(256, 2)
void scores_k(const __half* __restrict__ Q, const __half* __restrict__ Kp,
              __half* __restrict__ P, float* __restrict__ rsp)
{
    __shared__ __half As[128][72];
    __shared__ __half Bs[128][72];
    __shared__ float  srs[512];

    const int tid  = threadIdx.x;
    const int warp = tid >> 5, lane = tid & 31;
    const int gid = lane >> 2, tg = lane & 3;
    const int wm0 = (warp >> 2) * 64;
    const int wn0 = (warp & 3) * 32;
    const int gm0 = blockIdx.y * 128, gn0 = blockIdx.x * 128;

    const __half* Ah = Q  + (long)blockIdx.z * T_LEN * HD + (long)gm0 * HD;
    const __half* Bh = Kp + (long)blockIdx.z * T_LEN * HD + (long)gn0 * HD;

#pragma unroll
    for (int i = 0; i < 4; i++) {
        const int idx = (tid + i * 256) * 8;
        const int m = idx >> 6, k = idx & 63;
        *(uint4*)&As[m][k] = *(const uint4*)(Ah + (long)m * 64 + k);
    }
#pragma unroll
    for (int i = 0; i < 4; i++) {
        const int idx = (tid + i * 256) * 8;
        const int m = idx >> 6, k = idx & 63;
        *(uint4*)&Bs[m][k] = *(const uint4*)(Bh + (long)m * 64 + k);
    }
    __syncthreads();

    // LDSM lane addresses (byte offsets advance by ks*2 per k-step)
    uint32_t aAddr[4], bAddr[2];
#pragma unroll
    for (int i = 0; i < 4; i++)
        aAddr[i] = smem_u32(&As[wm0 + i*16 + (lane & 15)][(lane >> 4) * 8]);
#pragma unroll
    for (int jp = 0; jp < 2; jp++)
        bAddr[jp] = smem_u32(&Bs[wn0 + jp*16 + (lane & 7) + ((lane >> 4) << 3)]
                               [((lane >> 3) & 1) * 8]);

    float acc[4][4][4];
#pragma unroll
    for (int i = 0; i < 4; i++)
#pragma unroll
        for (int j = 0; j < 4; j++)
#pragma unroll
            for (int q = 0; q < 4; q++) acc[i][j][q] = 0.0f;

#pragma unroll
    for (int ks = 0; ks < 64; ks += 16) {
        uint32_t af[4][4], bq[2][4];
#pragma unroll
        for (int i = 0; i < 4; i++) ldsm_x4(af[i], aAddr[i] + ks * 2);
#pragma unroll
        for (int jp = 0; jp < 2; jp++) ldsm_x4(bq[jp], bAddr[jp] + ks * 2);
#pragma unroll
        for (int i = 0; i < 4; i++)
#pragma unroll
            for (int j = 0; j < 4; j++)
                mma_f16(acc[i][j], af[i][0], af[i][1], af[i][2], af[i][3],
                        bq[j >> 1][(j & 1) * 2], bq[j >> 1][(j & 1) * 2 + 1]);
    }

    // epilogue: p = 2^(s*log2e + 2) fp16, fp32 row-sum partials
    float rsum[4][2];
#pragma unroll
    for (int i = 0; i < 4; i++) { rsum[i][0] = 0.f; rsum[i][1] = 0.f; }

    __half* Ch = P + (long)blockIdx.z * T_LEN * T_LEN;
#pragma unroll
    for (int i = 0; i < 4; i++) {
#pragma unroll
        for (int j = 0; j < 4; j++) {
#pragma unroll
            for (int h2 = 0; h2 < 2; h2++) {
                const int m = gm0 + wm0 + i * 16 + gid + h2 * 8;
                const int n = gn0 + wn0 + j * 8 + tg * 2;
                float v0 = ex2(fmaf(acc[i][j][h2 * 2 + 0], LOG2E, PSHIFT));
                float v1 = ex2(fmaf(acc[i][j][h2 * 2 + 1], LOG2E, PSHIFT));
                rsum[i][h2] += v0 + v1;
                *(__half2*)(Ch + (long)m * T_LEN + n) = __floats2half2_rn(v0, v1);
            }
        }
    }
#pragma unroll
    for (int i = 0; i < 4; i++)
#pragma unroll
        for (int h2 = 0; h2 < 2; h2++)
#pragma unroll
            for (int o = 1; o < 4; o <<= 1)
                rsum[i][h2] += __shfl_xor_sync(0xffffffffu, rsum[i][h2], o);
    if (tg == 0) {
        const int wn = warp & 3;
#pragma unroll
        for (int i = 0; i < 4; i++)
#pragma unroll
            for (int h2 = 0; h2 < 2; h2++)
                srs[wn * 128 + wm0 + i * 16 + h2 * 8 + gid] = rsum[i][h2];
    }
    __syncthreads();
    if (tid < 128) {
        float s = srs[tid] + srs[128 + tid] + srs[256 + tid] + srs[384 + tid];
        rsp[((long)blockIdx.z * T_LEN + gm0 + tid) * NBX_SCORES + blockIdx.x] = s;
    }
}

// ===========================================================================
// Generic fp16-MMA GEMM, double-buffered, BK=32, LDSM fragment loads.
//   A (M,K) rm; B (N,K) rm. AH/BH: operand already fp16 (else fp32 converted).
//   CH: C fp16. NORMROW: scale row m by rowinv[m].
//   EPI 0: C[m*ldc+n]; 1: [h][m][d]; 2: [h][d][m]  (h=n>>6, d=n&63)
//   NT must be even (B ldmatrix pairs tiles).
// ===========================================================================
template<int BM, int BN, int WARPS_M, int WARPS_N,
         int EPI, bool AH, bool BH, bool NORMROW, bool CH>
__global__ __launch_bounds__(WARPS_M*WARPS_N*32)
void gemm_k(const void* __restrict__ Av, const void* __restrict__ Bv,
            const float* __restrict__ bias, void* __restrict__ Cv,
            const float* __restrict__ rowinv,
            int M, int N, int K, int ldc,
            long aH, long bH, long cH, long riH, float scale)
{
    constexpr int THREADS = WARPS_M*WARPS_N*32;
    constexpr int BK = 32;
    constexpr int WM = BM/WARPS_M, WN = BN/WARPS_N;
    constexpr int MT = WM/16, NT = WN/8;
    static_assert(NT % 2 == 0, "NT must be even for paired B ldmatrix");

    const float*  Af  = (const float*) Av + (AH ? 0 : blockIdx.z * aH);
    const __half* Ahp = (const __half*)Av + (AH ? blockIdx.z * aH : 0);
    const float*  Bf  = (const float*) Bv + (BH ? 0 : blockIdx.z * bH);
    const __half* Bhp = (const __half*)Bv + (BH ? blockIdx.z * bH : 0);
    float*  Cf  = (float*) Cv + (CH ? 0 : blockIdx.z * cH);
    __half* Chp = (__half*)Cv + (CH ? blockIdx.z * cH : 0);
    if (NORMROW) rowinv += blockIdx.z * riH;

    __shared__ __half As[2][BM][40];
    __shared__ __half Bs[2][BN][40];

    const int tid  = threadIdx.x;
    const int warp = tid >> 5, lane = tid & 31;
    const int wm0 = (warp / WARPS_N) * WM;
    const int wn0 = (warp % WARPS_N) * WN;
    const int gid = lane >> 2, tg = lane & 3;
    const int gm0 = blockIdx.y * BM, gn0 = blockIdx.x * BN;

    constexpr int AC = AH ? BM*BK/(THREADS*8) : BM*BK/(THREADS*4);
    constexpr int BC = BH ? BN*BK/(THREADS*8) : BN*BK/(THREADS*4);
    int am[AC], ak[AC], bn[BC], bk[BC];
#pragma unroll
    for (int i = 0; i < AC; i++) {
        int idx = (tid + i*THREADS) * (AH ? 8 : 4);
        am[i] = idx / BK; ak[i] = idx % BK;
    }
#pragma unroll
    for (int i = 0; i < BC; i++) {
        int idx = (tid + i*THREADS) * (BH ? 8 : 4);
        bn[i] = idx / BK; bk[i] = idx % BK;
    }

    // LDSM lane byte-offsets within one buffer
    constexpr uint32_t A_BUF = BM * 40 * 2;   // bytes per As buffer
    constexpr uint32_t B_BUF = BN * 40 * 2;
    uint32_t aAddr0[MT], bAddr0[NT/2];
#pragma unroll
    for (int i = 0; i < MT; i++)
        aAddr0[i] = smem_u32(&As[0][wm0 + i*16 + (lane & 15)][(lane >> 4) * 8]);
#pragma unroll
    for (int jp = 0; jp < NT/2; jp++)
        bAddr0[jp] = smem_u32(&Bs[0][wn0 + jp*16 + (lane & 7) + ((lane >> 4) << 3)]
                                 [((lane >> 3) & 1) * 8]);

    uint4  ra16[AC], rb16[BC];
    float4 ra32[AC], rb32[BC];
    auto loadg = [&](int k0) {
#pragma unroll
        for (int i = 0; i < AC; i++) {
            if (AH) ra16[i] = *(const uint4*)(Ahp + (long)(gm0 + am[i])*K + k0 + ak[i]);
            else    ra32[i] = *(const float4*)(Af + (long)(gm0 + am[i])*K + k0 + ak[i]);
        }
#pragma unroll
        for (int i = 0; i < BC; i++) {
            if (BH) rb16[i] = *(const uint4*)(Bhp + (long)(gn0 + bn[i])*K + k0 + bk[i]);
            else    rb32[i] = *(const float4*)(Bf + (long)(gn0 + bn[i])*K + k0 + bk[i]);
        }
    };
    auto sts = [&](int buf) {
#pragma unroll
        for (int i = 0; i < AC; i++) {
            if (AH) *(uint4*)&As[buf][am[i]][ak[i]] = ra16[i];
            else {
                __half2 lo = __floats2half2_rn(ra32[i].x, ra32[i].y);
                __half2 hi = __floats2half2_rn(ra32[i].z, ra32[i].w);
                *(__half2*)&As[buf][am[i]][ak[i]    ] = lo;
                *(__half2*)&As[buf][am[i]][ak[i] + 2] = hi;
            }
        }
#pragma unroll
        for (int i = 0; i < BC; i++) {
            if (BH) *(uint4*)&Bs[buf][bn[i]][bk[i]] = rb16[i];
            else {
                __half2 lo = __floats2half2_rn(rb32[i].x, rb32[i].y);
                __half2 hi = __floats2half2_rn(rb32[i].z, rb32[i].w);
                *(__half2*)&Bs[buf][bn[i]][bk[i]    ] = lo;
                *(__half2*)&Bs[buf][bn[i]][bk[i] + 2] = hi;
            }
        }
    };

    float acc[MT][NT][4];
#pragma unroll
    for (int i = 0; i < MT; i++)
#pragma unroll
        for (int j = 0; j < NT; j++)
#pragma unroll
            for (int q = 0; q < 4; q++) acc[i][j][q] = 0.0f;

    const int NI = K / BK;
    loadg(0);
    sts(0);
#pragma unroll 1
    for (int it = 0; it < NI; ++it) {
        __syncthreads();
        if (it + 1 < NI) loadg((it + 1) * BK);
        const int buf = it & 1;
        const uint32_t aB = buf * A_BUF, bB = buf * B_BUF;
#pragma unroll
        for (int ks = 0; ks < BK; ks += 16) {
            uint32_t af[MT][4], bq[NT/2][4];
#pragma unroll
            for (int i = 0; i < MT; i++) ldsm_x4(af[i], aAddr0[i] + aB + ks * 2);
#pragma unroll
            for (int jp = 0; jp < NT/2; jp++) ldsm_x4(bq[jp], bAddr0[jp] + bB + ks * 2);
#pragma unroll
            for (int i = 0; i < MT; i++)
#pragma unroll
                for (int j = 0; j < NT; j++)
                    mma_f16(acc[i][j], af[i][0], af[i][1], af[i][2], af[i][3],
                            bq[j >> 1][(j & 1) * 2], bq[j >> 1][(j & 1) * 2 + 1]);
        }
        if (it + 1 < NI) sts(buf ^ 1);
    }

#pragma unroll
    for (int i = 0; i < MT; i++) {
#pragma unroll
        for (int j = 0; j < NT; j++) {
#pragma unroll
            for (int h2 = 0; h2 < 2; h2++) {
                int m = gm0 + wm0 + i*16 + gid + h2*8;
                int n = gn0 + wn0 + j*8 + tg*2;
                float v0 = acc[i][j][h2*2 + 0];
                float v1 = acc[i][j][h2*2 + 1];
                if (bias) { v0 += bias[n]; v1 += bias[n+1]; }
                float sc = NORMROW ? rowinv[m] : scale;
                v0 *= sc; v1 *= sc;
                if (EPI == 0) {
                    if (CH) *(__half2*)(Chp + (long)m*ldc + n) = __floats2half2_rn(v0, v1);
                    else    *(float2*)(Cf + (long)m*ldc + n) = make_float2(v0, v1);
                } else if (EPI == 1) {          // [h][m][d]
                    int h = n >> 6, d = n & 63;
                    *(__half2*)(Chp + (long)h*M*HD + (long)m*HD + d) =
                        __floats2half2_rn(v0, v1);
                } else {                        // [h][d][m]
                    int h = n >> 6, d = n & 63;
                    __half* p = Chp + (long)h*HD*M + (long)d*M + m;
                    p[0] = __float2half_rn(v0);
                    p[M] = __float2half_rn(v1);
                }
            }
        }
    }
}

// ---------------------------------------------------------------------------
__global__ __launch_bounds__(256) void invred_k(const float* __restrict__ part,
                                                float* __restrict__ inv)
{
    const int warp = threadIdx.x >> 5, lane = threadIdx.x & 31;
    const long row = (long)blockIdx.x * 8 + warp;
    float s = part[row * 32 + lane];
#pragma unroll
    for (int o = 16; o > 0; o >>= 1)
        s += __shfl_xor_sync(0xffffffffu, s, o);
    if (lane == 0) inv[row] = 1.0f / s;
}

// ---------------------------------------------------------------------------
__global__ __launch_bounds__(1024) void avg_k(const __half* __restrict__ P,
                                              const float* __restrict__ inv,
                                              float* __restrict__ out)
{
    const int t = blockIdx.x, tid = threadIdx.x;
    const long TS = (long)T_LEN * T_LEN;
    const __half* base = P + (long)t * T_LEN + tid * 4;
    float4 acc = make_float4(0.f, 0.f, 0.f, 0.f);
#pragma unroll
    for (int h = 0; h < H_NUM; h++) {
        const float iv = inv[h * T_LEN + t] * (1.0f / H_NUM);
        uint2 u = *(const uint2*)(base + (long)h * TS);
        float2 lo = __half22float2(*(__half2*)&u.x);
        float2 hi = __half22float2(*(__half2*)&u.y);
        acc.x += lo.x * iv; acc.y += lo.y * iv;
        acc.z += hi.x * iv; acc.w += hi.y * iv;
    }
    ((float4*)(out + (long)t * T_LEN))[tid] = acc;
}

// ---------------------------------------------------------------------------
extern "C" void kernel_launch(void* const* d_in, const int* in_sizes, int n_in,
                              void* d_out, int out_size)
{
    const float* q_in = (const float*)d_in[0];
    const float* k_in = (const float*)d_in[1];
    const float* v_in = (const float*)d_in[2];
    const float* w    = (const float*)d_in[3];
    const float* b    = (const float*)d_in[4];
    const float* ow   = (const float*)d_in[5];
    const float* ob   = (const float*)d_in[6];
    float* out = (float*)d_out;

    __half *Q, *K, *Vt, *P, *CTX;
    float *RSP, *INV;
    cudaGetSymbolAddress((void**)&Q,   g_Q);
    cudaGetSymbolAddress((void**)&K,   g_K);
    cudaGetSymbolAddress((void**)&Vt,  g_Vt);
    cudaGetSymbolAddress((void**)&P,   g_P);
    cudaGetSymbolAddress((void**)&CTX, g_CTX);
    cudaGetSymbolAddress((void**)&RSP, g_RSP);
    cudaGetSymbolAddress((void**)&INV, g_INV);

    const int T = T_LEN, E = E_DIM, H = H_NUM;
    const long EE = (long)E * E;
    dim3 blk(256);

    // QKV projections: fp32 in -> fp16 head-major out
    gemm_k<128,128,2,4,1,false,false,false,true><<<dim3(E/128, T/128, 1), blk>>>(
        q_in, w,        b,       Q,  nullptr, T, E, E, 0, 0,0,0,0, 0.125f);
    gemm_k<128,128,2,4,1,false,false,false,true><<<dim3(E/128, T/128, 1), blk>>>(
        k_in, w + EE,   b + E,   K,  nullptr, T, E, E, 0, 0,0,0,0, 1.0f);
    gemm_k<128,128,2,4,2,false,false,false,true><<<dim3(E/128, T/128, 1), blk>>>(
        v_in, w + 2*EE, b + 2*E, Vt, nullptr, T, E, E, 0, 0,0,0,0, 1.0f);

    // scores -> fp16 P + partial row sums
    scores_k<<<dim3(T/128, T/128, H), blk>>>(Q, K, P, RSP);

    // row-sum reduce -> inv
    invred_k<<<(H*T)/8, 256>>>(RSP, INV);

    // head-average -> second half of d_out
    avg_k<<<T, 1024>>>(P, INV, out + (long)T * E);

    // ctx: CTX[t, h*64+d] = inv[h][t] * (P16[h] @ Vt16[h]^T)   (fp16 out)
    gemm_k<128,64,4,2,0,true,true,true,true><<<dim3(1, T/128, H), blk>>>(
        P, Vt, nullptr, CTX, INV, T, HD, T, E,
        (long)T*T, (long)HD*T, 64, T, 1.0f);

    // out projection: fp16 CTX @ fp32 W^T + bias -> fp32 out
    gemm_k<128,128,2,4,0,true,false,false,false><<<dim3(E/128, T/128, 1), blk>>>(
        CTX, ow, ob, out, nullptr, T, E, E, E, 0,0,0,0, 1.0f);
}

// round 9
// speedup vs baseline: 4.9405x; 1.0763x over previous
#include <cuda_runtime.h>
#include <cuda_fp16.h>
#include <cstdint>

#define T_LEN 4096
#define E_DIM 1024
#define H_NUM 16
#define HD    64
#define NBX_SCORES 4     // column splits in scores kernel
#define NT_SC 8          // K-tiles per scores block (T/128/NBX_SCORES)

// Scratch (allocation-free rule: __device__ globals)
__device__ __half g_Q  [(long)H_NUM * T_LEN * HD];    // [h][t][d] fp16
__device__ __half g_K  [(long)H_NUM * T_LEN * HD];    // [h][t][d] fp16
__device__ __half g_Vt [(long)H_NUM * HD * T_LEN];    // [h][d][t] fp16
__device__ __half g_P  [(long)H_NUM * T_LEN * T_LEN]; // [h][t][s] scaled exp fp16
__device__ __half g_CTX[(long)T_LEN * E_DIM];         // [t][e] fp16
__device__ float  g_RSP[(long)H_NUM * T_LEN * NBX_SCORES];
__device__ float  g_INV[(long)H_NUM * T_LEN];         // 1/rowsum

__device__ __forceinline__ float ex2(float x) {
    float r;
    asm("ex2.approx.f32 %0, %1;" : "=f"(r) : "f"(x));
    return r;
}

__device__ __forceinline__ uint32_t smem_u32(const void* p) {
    return (uint32_t)__cvta_generic_to_shared(p);
}

__device__ __forceinline__ void ldsm_x4(uint32_t r[4], uint32_t addr) {
    asm volatile("ldmatrix.sync.aligned.m8n8.x4.shared.b16 {%0,%1,%2,%3}, [%4];"
        : "=r"(r[0]), "=r"(r[1]), "=r"(r[2]), "=r"(r[3]) : "r"(addr));
}

__device__ __forceinline__ void cp_async16(uint32_t saddr, const void* gaddr) {
    asm volatile("cp.async.cg.shared.global [%0], [%1], 16;"
        :: "r"(saddr), "l"(gaddr));
}
__device__ __forceinline__ void cp_commit() {
    asm volatile("cp.async.commit_group;");
}
template<int N>
__device__ __forceinline__ void cp_wait() {
    asm volatile("cp.async.wait_group %0;" :: "n"(N));
}

// fp16 MMA, fp32 accum
__device__ __forceinline__ void mma_f16(float c[4],
    uint32_t a0, uint32_t a1, uint32_t a2, uint32_t a3,
    uint32_t b0, uint32_t b1)
{
    asm volatile(
        "mma.sync.aligned.m16n8k16.row.col.f32.f16.f16.f32 "
        "{%0,%1,%2,%3}, {%4,%5,%6,%7}, {%8,%9}, {%0,%1,%2,%3};"
        : "+f"(c[0]), "+f"(c[1]), "+f"(c[2]), "+f"(c[3])
        : "r"(a0), "r"(a1), "r"(a2), "r"(a3), "r"(b0), "r"(b1));
}

#define LOG2E 1.4426950408889634f
#define PSHIFT 2.0f   // p = 2^(s*log2e + 2)

// ===========================================================================
// Scores, pipelined: block = (128 q-rows) x (8 K-tiles of 128), head z.
// Q tile resident in regs after one LDSM pass; K tiles double-buffered
// via cp.async. P[h] = fp16(2^(s*log2e+2)); fp32 row-sum partials (4/row).
// grid (NBX_SCORES, T/128, H), 256 thr, 8 warps (2x4), warp tile 64x32.
// ===========================================================================
__global__ __launch_bounds__(256, 2)
void scores_k(const __half* __restrict__ Q, const __half* __restrict__ Kp,
              __half* __restrict__ P, float* __restrict__ rsp)
{
    __shared__ __half Qs[128][72];
    __shared__ __half Ks[2][128][72];
    __shared__ float  srs[512];

    const int tid  = threadIdx.x;
    const int warp = tid >> 5, lane = tid & 31;
    const int gid = lane >> 2, tg = lane & 3;
    const int wm0 = (warp >> 2) * 64;
    const int wn0 = (warp & 3) * 32;
    const int gm0 = blockIdx.y * 128;
    const int cbase = blockIdx.x * (NT_SC * 128);

    const __half* Ah = Q  + (long)blockIdx.z * T_LEN * HD + (long)gm0 * HD;
    const __half* Kh = Kp + (long)blockIdx.z * T_LEN * HD + (long)cbase * HD;

    // load indices (4 passes of 16B per tile)
    int lm[4], lk[4];
#pragma unroll
    for (int i = 0; i < 4; i++) {
        const int idx = (tid + i * 256) * 8;
        lm[i] = idx >> 6; lk[i] = idx & 63;
    }

    auto prefetchK = [&](int nt, int buf) {
#pragma unroll
        for (int i = 0; i < 4; i++)
            cp_async16(smem_u32(&Ks[buf][lm[i]][lk[i]]),
                       Kh + ((long)nt * 128 + lm[i]) * HD + lk[i]);
    };

    // group 0: Q + K0 ; group 1: K1
#pragma unroll
    for (int i = 0; i < 4; i++)
        cp_async16(smem_u32(&Qs[lm[i]][lk[i]]), Ah + (long)lm[i] * HD + lk[i]);
    prefetchK(0, 0);
    cp_commit();
    prefetchK(1, 1);
    cp_commit();
    cp_wait<1>();           // Q + K0 ready
    __syncthreads();

    // Q fragments: load once, reuse for all 8 K-tiles
    uint32_t af[4][4][4];   // [ks16][mt][reg]
#pragma unroll
    for (int i = 0; i < 4; i++) {
        const uint32_t a = smem_u32(&Qs[wm0 + i*16 + (lane & 15)][(lane >> 4) * 8]);
#pragma unroll
        for (int ks = 0; ks < 4; ks++) ldsm_x4(af[ks][i], a + ks * 32);
    }

    // K-tile LDSM base addresses per buffer
    uint32_t bAddr[2][2];
#pragma unroll
    for (int buf = 0; buf < 2; buf++)
#pragma unroll
        for (int jp = 0; jp < 2; jp++)
            bAddr[buf][jp] = smem_u32(
                &Ks[buf][wn0 + jp*16 + (lane & 7) + ((lane >> 4) << 3)]
                        [((lane >> 3) & 1) * 8]);

    float rsum[4][2];
#pragma unroll
    for (int i = 0; i < 4; i++) { rsum[i][0] = 0.f; rsum[i][1] = 0.f; }

    __half* Ch = P + (long)blockIdx.z * T_LEN * T_LEN;

#pragma unroll 1
    for (int nt = 0; nt < NT_SC; nt++) {
        const int buf = nt & 1;

        float acc[4][4][4];
#pragma unroll
        for (int i = 0; i < 4; i++)
#pragma unroll
            for (int j = 0; j < 4; j++)
#pragma unroll
                for (int q = 0; q < 4; q++) acc[i][j][q] = 0.0f;

#pragma unroll
        for (int ks = 0; ks < 4; ks++) {
            uint32_t bq[2][4];
#pragma unroll
            for (int jp = 0; jp < 2; jp++)
                ldsm_x4(bq[jp], bAddr[buf][jp] + ks * 32);
#pragma unroll
            for (int i = 0; i < 4; i++)
#pragma unroll
                for (int j = 0; j < 4; j++)
                    mma_f16(acc[i][j], af[ks][i][0], af[ks][i][1],
                            af[ks][i][2], af[ks][i][3],
                            bq[j >> 1][(j & 1) * 2], bq[j >> 1][(j & 1) * 2 + 1]);
        }

        // epilogue for this tile (overlaps next tile's cp.async)
        const int n0t = cbase + nt * 128;
#pragma unroll
        for (int i = 0; i < 4; i++) {
#pragma unroll
            for (int j = 0; j < 4; j++) {
#pragma unroll
                for (int h2 = 0; h2 < 2; h2++) {
                    const int m = gm0 + wm0 + i * 16 + gid + h2 * 8;
                    const int n = n0t + wn0 + j * 8 + tg * 2;
                    float v0 = ex2(fmaf(acc[i][j][h2 * 2 + 0], LOG2E, PSHIFT));
                    float v1 = ex2(fmaf(acc[i][j][h2 * 2 + 1], LOG2E, PSHIFT));
                    rsum[i][h2] += v0 + v1;
                    *(__half2*)(Ch + (long)m * T_LEN + n) = __floats2half2_rn(v0, v1);
                }
            }
        }

        __syncthreads();                       // everyone done reading Ks[buf]
        if (nt + 2 < NT_SC) { prefetchK(nt + 2, buf); cp_commit(); }
        if (nt + 1 < NT_SC) {
            if (nt + 2 < NT_SC) cp_wait<1>(); else cp_wait<0>();
            __syncthreads();                   // Ks[buf^1] ready
        }
    }

    // row-sum partials
#pragma unroll
    for (int i = 0; i < 4; i++)
#pragma unroll
        for (int h2 = 0; h2 < 2; h2++)
#pragma unroll
            for (int o = 1; o < 4; o <<= 1)
                rsum[i][h2] += __shfl_xor_sync(0xffffffffu, rsum[i][h2], o);
    if (tg == 0) {
        const int wn = warp & 3;
#pragma unroll
        for (int i = 0; i < 4; i++)
#pragma unroll
            for (int h2 = 0; h2 < 2; h2++)
                srs[wn * 128 + wm0 + i * 16 + h2 * 8 + gid] = rsum[i][h2];
    }
    __syncthreads();
    if (tid < 128) {
        float s = srs[tid] + srs[128 + tid] + srs[256 + tid] + srs[384 + tid];
        rsp[((long)blockIdx.z * T_LEN + gm0 + tid) * NBX_SCORES + blockIdx.x] = s;
    }
}

// ===========================================================================
// Generic fp16-MMA GEMM, double-buffered, BK=32, LDSM fragment loads.
// (unchanged from R8)
// ===========================================================================
template<int BM, int BN, int WARPS_M, int WARPS_N,
         int EPI, bool AH, bool BH, bool NORMROW, bool CH>
__global__ __launch_bounds__(WARPS_M*WARPS_N*32)
void gemm_k(const void* __restrict__ Av, const void* __restrict__ Bv,
            const float* __restrict__ bias, void* __restrict__ Cv,
            const float* __restrict__ rowinv,
            int M, int N, int K, int ldc,
            long aH, long bH, long cH, long riH, float scale)
{
    constexpr int THREADS = WARPS_M*WARPS_N*32;
    constexpr int BK = 32;
    constexpr int WM = BM/WARPS_M, WN = BN/WARPS_N;
    constexpr int MT = WM/16, NT = WN/8;
    static_assert(NT % 2 == 0, "NT must be even");

    const float*  Af  = (const float*) Av + (AH ? 0 : blockIdx.z * aH);
    const __half* Ahp = (const __half*)Av + (AH ? blockIdx.z * aH : 0);
    const float*  Bf  = (const float*) Bv + (BH ? 0 : blockIdx.z * bH);
    const __half* Bhp = (const __half*)Bv + (BH ? blockIdx.z * bH : 0);
    float*  Cf  = (float*) Cv + (CH ? 0 : blockIdx.z * cH);
    __half* Chp = (__half*)Cv + (CH ? blockIdx.z * cH : 0);
    if (NORMROW) rowinv += blockIdx.z * riH;

    __shared__ __half As[2][BM][40];
    __shared__ __half Bs[2][BN][40];

    const int tid  = threadIdx.x;
    const int warp = tid >> 5, lane = tid & 31;
    const int wm0 = (warp / WARPS_N) * WM;
    const int wn0 = (warp % WARPS_N) * WN;
    const int gid = lane >> 2, tg = lane & 3;
    const int gm0 = blockIdx.y * BM, gn0 = blockIdx.x * BN;

    constexpr int AC = AH ? BM*BK/(THREADS*8) : BM*BK/(THREADS*4);
    constexpr int BC = BH ? BN*BK/(THREADS*8) : BN*BK/(THREADS*4);
    int am[AC], ak[AC], bn[BC], bk[BC];
#pragma unroll
    for (int i = 0; i < AC; i++) {
        int idx = (tid + i*THREADS) * (AH ? 8 : 4);
        am[i] = idx / BK; ak[i] = idx % BK;
    }
#pragma unroll
    for (int i = 0; i < BC; i++) {
        int idx = (tid + i*THREADS) * (BH ? 8 : 4);
        bn[i] = idx / BK; bk[i] = idx % BK;
    }

    constexpr uint32_t A_BUF = BM * 40 * 2;
    constexpr uint32_t B_BUF = BN * 40 * 2;
    uint32_t aAddr0[MT], bAddr0[NT/2];
#pragma unroll
    for (int i = 0; i < MT; i++)
        aAddr0[i] = smem_u32(&As[0][wm0 + i*16 + (lane & 15)][(lane >> 4) * 8]);
#pragma unroll
    for (int jp = 0; jp < NT/2; jp++)
        bAddr0[jp] = smem_u32(&Bs[0][wn0 + jp*16 + (lane & 7) + ((lane >> 4) << 3)]
                                 [((lane >> 3) & 1) * 8]);

    uint4  ra16[AC], rb16[BC];
    float4 ra32[AC], rb32[BC];
    auto loadg = [&](int k0) {
#pragma unroll
        for (int i = 0; i < AC; i++) {
            if (AH) ra16[i] = *(const uint4*)(Ahp + (long)(gm0 + am[i])*K + k0 + ak[i]);
            else    ra32[i] = *(const float4*)(Af + (long)(gm0 + am[i])*K + k0 + ak[i]);
        }
#pragma unroll
        for (int i = 0; i < BC; i++) {
            if (BH) rb16[i] = *(const uint4*)(Bhp + (long)(gn0 + bn[i])*K + k0 + bk[i]);
            else    rb32[i] = *(const float4*)(Bf + (long)(gn0 + bn[i])*K + k0 + bk[i]);
        }
    };
    auto sts = [&](int buf) {
#pragma unroll
        for (int i = 0; i < AC; i++) {
            if (AH) *(uint4*)&As[buf][am[i]][ak[i]] = ra16[i];
            else {
                __half2 lo = __floats2half2_rn(ra32[i].x, ra32[i].y);
                __half2 hi = __floats2half2_rn(ra32[i].z, ra32[i].w);
                *(__half2*)&As[buf][am[i]][ak[i]    ] = lo;
                *(__half2*)&As[buf][am[i]][ak[i] + 2] = hi;
            }
        }
#pragma unroll
        for (int i = 0; i < BC; i++) {
            if (BH) *(uint4*)&Bs[buf][bn[i]][bk[i]] = rb16[i];
            else {
                __half2 lo = __floats2half2_rn(rb32[i].x, rb32[i].y);
                __half2 hi = __floats2half2_rn(rb32[i].z, rb32[i].w);
                *(__half2*)&Bs[buf][bn[i]][bk[i]    ] = lo;
                *(__half2*)&Bs[buf][bn[i]][bk[i] + 2] = hi;
            }
        }
    };

    float acc[MT][NT][4];
#pragma unroll
    for (int i = 0; i < MT; i++)
#pragma unroll
        for (int j = 0; j < NT; j++)
#pragma unroll
            for (int q = 0; q < 4; q++) acc[i][j][q] = 0.0f;

    const int NI = K / BK;
    loadg(0);
    sts(0);
#pragma unroll 1
    for (int it = 0; it < NI; ++it) {
        __syncthreads();
        if (it + 1 < NI) loadg((it + 1) * BK);
        const int buf = it & 1;
        const uint32_t aB = buf * A_BUF, bB = buf * B_BUF;
#pragma unroll
        for (int ks = 0; ks < BK; ks += 16) {
            uint32_t af[MT][4], bq[NT/2][4];
#pragma unroll
            for (int i = 0; i < MT; i++) ldsm_x4(af[i], aAddr0[i] + aB + ks * 2);
#pragma unroll
            for (int jp = 0; jp < NT/2; jp++) ldsm_x4(bq[jp], bAddr0[jp] + bB + ks * 2);
#pragma unroll
            for (int i = 0; i < MT; i++)
#pragma unroll
                for (int j = 0; j < NT; j++)
                    mma_f16(acc[i][j], af[i][0], af[i][1], af[i][2], af[i][3],
                            bq[j >> 1][(j & 1) * 2], bq[j >> 1][(j & 1) * 2 + 1]);
        }
        if (it + 1 < NI) sts(buf ^ 1);
    }

#pragma unroll
    for (int i = 0; i < MT; i++) {
#pragma unroll
        for (int j = 0; j < NT; j++) {
#pragma unroll
            for (int h2 = 0; h2 < 2; h2++) {
                int m = gm0 + wm0 + i*16 + gid + h2*8;
                int n = gn0 + wn0 + j*8 + tg*2;
                float v0 = acc[i][j][h2*2 + 0];
                float v1 = acc[i][j][h2*2 + 1];
                if (bias) { v0 += bias[n]; v1 += bias[n+1]; }
                float sc = NORMROW ? rowinv[m] : scale;
                v0 *= sc; v1 *= sc;
                if (EPI == 0) {
                    if (CH) *(__half2*)(Chp + (long)m*ldc + n) = __floats2half2_rn(v0, v1);
                    else    *(float2*)(Cf + (long)m*ldc + n) = make_float2(v0, v1);
                } else if (EPI == 1) {
                    int h = n >> 6, d = n & 63;
                    *(__half2*)(Chp + (long)h*M*HD + (long)m*HD + d) =
                        __floats2half2_rn(v0, v1);
                } else {
                    int h = n >> 6, d = n & 63;
                    __half* p = Chp + (long)h*HD*M + (long)d*M + m;
                    p[0] = __float2half_rn(v0);
                    p[M] = __float2half_rn(v1);
                }
            }
        }
    }
}

// ---------------------------------------------------------------------------
// inv[row] = 1 / sum_{b<4} part[row*4+b]
// ---------------------------------------------------------------------------
__global__ __launch_bounds__(256) void invred_k(const float* __restrict__ part,
                                                float* __restrict__ inv)
{
    const long row = (long)blockIdx.x * 256 + threadIdx.x;
    const float4 p = ((const float4*)part)[row];
    inv[row] = 1.0f / ((p.x + p.y) + (p.z + p.w));
}

// ---------------------------------------------------------------------------
__global__ __launch_bounds__(1024) void avg_k(const __half* __restrict__ P,
                                              const float* __restrict__ inv,
                                              float* __restrict__ out)
{
    const int t = blockIdx.x, tid = threadIdx.x;
    const long TS = (long)T_LEN * T_LEN;
    const __half* base = P + (long)t * T_LEN + tid * 4;
    float4 acc = make_float4(0.f, 0.f, 0.f, 0.f);
#pragma unroll
    for (int h = 0; h < H_NUM; h++) {
        const float iv = inv[h * T_LEN + t] * (1.0f / H_NUM);
        uint2 u = *(const uint2*)(base + (long)h * TS);
        float2 lo = __half22float2(*(__half2*)&u.x);
        float2 hi = __half22float2(*(__half2*)&u.y);
        acc.x += lo.x * iv; acc.y += lo.y * iv;
        acc.z += hi.x * iv; acc.w += hi.y * iv;
    }
    ((float4*)(out + (long)t * T_LEN))[tid] = acc;
}

// ---------------------------------------------------------------------------
extern "C" void kernel_launch(void* const* d_in, const int* in_sizes, int n_in,
                              void* d_out, int out_size)
{
    const float* q_in = (const float*)d_in[0];
    const float* k_in = (const float*)d_in[1];
    const float* v_in = (const float*)d_in[2];
    const float* w    = (const float*)d_in[3];
    const float* b    = (const float*)d_in[4];
    const float* ow   = (const float*)d_in[5];
    const float* ob   = (const float*)d_in[6];
    float* out = (float*)d_out;

    __half *Q, *K, *Vt, *P, *CTX;
    float *RSP, *INV;
    cudaGetSymbolAddress((void**)&Q,   g_Q);
    cudaGetSymbolAddress((void**)&K,   g_K);
    cudaGetSymbolAddress((void**)&Vt,  g_Vt);
    cudaGetSymbolAddress((void**)&P,   g_P);
    cudaGetSymbolAddress((void**)&CTX, g_CTX);
    cudaGetSymbolAddress((void**)&RSP, g_RSP);
    cudaGetSymbolAddress((void**)&INV, g_INV);

    const int T = T_LEN, E = E_DIM, H = H_NUM;
    const long EE = (long)E * E;
    dim3 blk(256);

    // QKV projections: fp32 in -> fp16 head-major out
    gemm_k<128,128,2,4,1,false,false,false,true><<<dim3(E/128, T/128, 1), blk>>>(
        q_in, w,        b,       Q,  nullptr, T, E, E, 0, 0,0,0,0, 0.125f);
    gemm_k<128,128,2,4,1,false,false,false,true><<<dim3(E/128, T/128, 1), blk>>>(
        k_in, w + EE,   b + E,   K,  nullptr, T, E, E, 0, 0,0,0,0, 1.0f);
    gemm_k<128,128,2,4,2,false,false,false,true><<<dim3(E/128, T/128, 1), blk>>>(
        v_in, w + 2*EE, b + 2*E, Vt, nullptr, T, E, E, 0, 0,0,0,0, 1.0f);

    // scores (pipelined) -> fp16 P + partial row sums
    scores_k<<<dim3(NBX_SCORES, T/128, H), blk>>>(Q, K, P, RSP);

    // row-sum reduce -> inv
    invred_k<<<(H*T)/256, 256>>>(RSP, INV);

    // head-average -> second half of d_out
    avg_k<<<T, 1024>>>(P, INV, out + (long)T * E);

    // ctx: CTX[t, h*64+d] = inv[h][t] * (P16[h] @ Vt16[h]^T)
    gemm_k<128,64,4,2,0,true,true,true,true><<<dim3(1, T/128, H), blk>>>(
        P, Vt, nullptr, CTX, INV, T, HD, T, E,
        (long)T*T, (long)HD*T, 64, T, 1.0f);

    // out projection: fp16 CTX @ fp32 W^T + bias -> fp32 out
    gemm_k<128,128,2,4,0,true,false,false,false><<<dim3(E/128, T/128, 1), blk>>>(
        CTX, ow, ob, out, nullptr, T, E, E, E, 0,0,0,0, 1.0f);
}